// round 13
// baseline (speedup 1.0000x reference)
#include <cuda_runtime.h>
#include <cuda_bf16.h>
#include <math.h>

#define NMAX 100000
#define EMAX 1600000
#define GMAX 256
#define HEADSN 4
#define SCAN_CHUNK 512

// ---------------- scratch ----------------
__device__ __align__(16) float g_A[(size_t)NMAX * 128];
__device__ __align__(16) float g_B[(size_t)NMAX * 128];
__device__ __align__(16) float g_C[(size_t)NMAX * 128];
__device__ __align__(16) float g_dis[NMAX];
__device__ __align__(16) int   g_deg[NMAX];               // zero-init; scan3 self-resets
__device__ __align__(16) int   g_rowptr[NMAX + 1];
__device__ __align__(16) int   g_cursor[NMAX];
__device__ __align__(16) int2  g_pack[EMAX];              // (src, bits(dis[src]))
__device__ __align__(16) int   g_blksum[1024];
__device__ __align__(16) float g_ss[NMAX * HEADSN];
__device__ __align__(16) float g_sd[NMAX * HEADSN];
__device__ __align__(16) float g_mean[128];               // zero-init; final blocks reset
__device__ __align__(16) float g_sq[128];
__device__ __align__(16) float g_scale[128];
__device__ __align__(16) float g_shift[128];
__device__ __align__(16) float g_psum[GMAX * 64];         // raw pool sums; self-reset
__device__ __align__(16) float g_cnt[GMAX];               // self-reset
__device__            int   g_tick[8];                    // zero-init tickets; self-reset

__device__ __forceinline__ float lrelu(float v) { return v > 0.f ? v : 0.2f * v; }
__device__ __forceinline__ unsigned f2tf(float f) {
    unsigned u; asm("cvt.rna.tf32.f32 %0, %1;" : "=r"(u) : "f"(f)); return u;
}

// ---------------- CSR build ----------------
// 4 edges per thread -> 4 independent atomic chains in flight
__global__ void k_deg_count(const int* __restrict__ colp, int* deg, int E) {
    int i0 = (blockIdx.x * blockDim.x + threadIdx.x) * 4;
#pragma unroll
    for (int k = 0; k < 4; ++k) {
        int i = i0 + k;
        if (i < E) atomicAdd(&deg[__ldg(colp + i)], 1);
    }
}
__global__ void k_scan1(const int* __restrict__ deg, int* blksum, int n) {
    __shared__ int sh[SCAN_CHUNK];
    int i = blockIdx.x * SCAN_CHUNK + threadIdx.x;
    sh[threadIdx.x] = (i < n) ? deg[i] : 0;
    __syncthreads();
    for (int off = SCAN_CHUNK / 2; off > 0; off >>= 1) {
        if (threadIdx.x < off) sh[threadIdx.x] += sh[threadIdx.x + off];
        __syncthreads();
    }
    if (threadIdx.x == 0) blksum[blockIdx.x] = sh[0];
}
__global__ void k_scan3_dis(int* __restrict__ deg, const int* __restrict__ blksum,
                            int* rowptr, int* cursor, float* dis, int n) {
    __shared__ int sh[SCAN_CHUNK];
    int tid = threadIdx.x, bid = blockIdx.x;
    int part = 0;
    for (int j = tid; j < bid; j += SCAN_CHUNK) part += __ldg(blksum + j);
    sh[tid] = part;
    __syncthreads();
    for (int off = SCAN_CHUNK / 2; off > 0; off >>= 1) {
        if (tid < off) sh[tid] += sh[tid + off];
        __syncthreads();
    }
    int base = sh[0];
    __syncthreads();
    int i = bid * SCAN_CHUNK + tid;
    int v = (i < n) ? deg[i] : 0;
    sh[tid] = v;
    __syncthreads();
    for (int off = 1; off < SCAN_CHUNK; off <<= 1) {
        int t = (tid >= off) ? sh[tid - off] : 0;
        __syncthreads();
        sh[tid] += t;
        __syncthreads();
    }
    if (i < n) {
        int excl = base + sh[tid] - v;
        rowptr[i] = excl;
        cursor[i] = excl;
        dis[i] = rsqrtf(1.0f + (float)v);
        if (i == n - 1) rowptr[n] = excl + v;
        deg[i] = 0;   // reset for next replay (deterministic)
    }
}
// 4 edges per thread
__global__ void k_csr_fill(const int* __restrict__ rowp, const int* __restrict__ colp,
                           const float* __restrict__ dis, int* cursor, int2* pack, int E) {
    int i0 = (blockIdx.x * blockDim.x + threadIdx.x) * 4;
    int c[4], r[4], pos[4];
#pragma unroll
    for (int k = 0; k < 4; ++k) {
        int i = i0 + k;
        if (i < E) { c[k] = __ldg(colp + i); r[k] = __ldg(rowp + i); }
    }
#pragma unroll
    for (int k = 0; k < 4; ++k) {
        int i = i0 + k;
        if (i < E) pos[k] = atomicAdd(&cursor[c[k]], 1);
    }
#pragma unroll
    for (int k = 0; k < 4; ++k) {
        int i = i0 + k;
        if (i < E) pack[pos[k]] = make_int2(r[k], __float_as_int(__ldg(dis + r[k])));
    }
}

// ---------------- split-TF32 GEMM (+ fused BN stats / GAT scores epilogues) ------------
template <int DIN, int DOUT, bool BIAS, bool AFFINE, bool STATS, bool SCORES>
__global__ void k_gemm(const float* __restrict__ X, const float* __restrict__ W,
                       const float* __restrict__ bias,
                       const float* __restrict__ sc_, const float* __restrict__ sh_,
                       float* __restrict__ out,
                       float* mean, float* sq, float* scale, float* shift,
                       const float* __restrict__ bng, const float* __restrict__ bnb,
                       int* ticket,
                       const float* __restrict__ asrc, const float* __restrict__ adst,
                       float* __restrict__ ssO, float* __restrict__ sdO, int n) {
    constexpr int NT = (DOUT >= 128) ? 64 : 128;
    constexpr int KT = (DIN < 32) ? DIN : 32;
    constexpr int NW = NT / 16;
    constexpr int XS = KT + 4;
    constexpr int WS = DOUT + 4;
    __shared__ unsigned Xh[NT * XS];
    __shared__ unsigned Xl[NT * XS];
    __shared__ unsigned Wh[KT * WS];
    __shared__ unsigned Wl[KT * WS];

    const int tid = threadIdx.x;
    const int wid = tid >> 5, lane = tid & 31;
    const int g = lane >> 2, tig = lane & 3;
    const int nsub = wid % NW, cgp = wid / NW;
    const int base = blockIdx.x * NT;

    float acc[8][4];
#pragma unroll
    for (int i = 0; i < 8; ++i)
#pragma unroll
        for (int j = 0; j < 4; ++j) acc[i][j] = 0.f;

    for (int kt = 0; kt < DIN; kt += KT) {
        for (int i = tid; i < NT * (KT / 4); i += 256) {
            int r = i / (KT / 4), c = i % (KT / 4);
            int node = base + r;
            float4 v = make_float4(0.f, 0.f, 0.f, 0.f);
            if (node < n) v = ((const float4*)X)[(size_t)node * (DIN / 4) + kt / 4 + c];
            if (AFFINE) {
                float4 sc = __ldg((const float4*)sc_ + kt / 4 + c);
                float4 sh = __ldg((const float4*)sh_ + kt / 4 + c);
                v.x = v.x * sc.x + sh.x; v.y = v.y * sc.y + sh.y;
                v.z = v.z * sc.z + sh.z; v.w = v.w * sc.w + sh.w;
            }
            unsigned* dh = &Xh[r * XS + c * 4];
            unsigned* dl = &Xl[r * XS + c * 4];
            unsigned h0 = f2tf(v.x), h1 = f2tf(v.y), h2 = f2tf(v.z), h3 = f2tf(v.w);
            dh[0] = h0; dh[1] = h1; dh[2] = h2; dh[3] = h3;
            dl[0] = f2tf(v.x - __uint_as_float(h0));
            dl[1] = f2tf(v.y - __uint_as_float(h1));
            dl[2] = f2tf(v.z - __uint_as_float(h2));
            dl[3] = f2tf(v.w - __uint_as_float(h3));
        }
        for (int i = tid; i < KT * (DOUT / 4); i += 256) {
            int r = i / (DOUT / 4), c = i % (DOUT / 4);
            float4 v = ((const float4*)W)[(size_t)(kt + r) * (DOUT / 4) + c];
            unsigned* dh = &Wh[r * WS + c * 4];
            unsigned* dl = &Wl[r * WS + c * 4];
            unsigned h0 = f2tf(v.x), h1 = f2tf(v.y), h2 = f2tf(v.z), h3 = f2tf(v.w);
            dh[0] = h0; dh[1] = h1; dh[2] = h2; dh[3] = h3;
            dl[0] = f2tf(v.x - __uint_as_float(h0));
            dl[1] = f2tf(v.y - __uint_as_float(h1));
            dl[2] = f2tf(v.z - __uint_as_float(h2));
            dl[3] = f2tf(v.w - __uint_as_float(h3));
        }
        __syncthreads();
#pragma unroll
        for (int ks = 0; ks < KT; ks += 8) {
            int r0 = nsub * 16 + g;
            unsigned ah0 = Xh[r0 * XS + ks + tig];
            unsigned ah1 = Xh[(r0 + 8) * XS + ks + tig];
            unsigned ah2 = Xh[r0 * XS + ks + tig + 4];
            unsigned ah3 = Xh[(r0 + 8) * XS + ks + tig + 4];
            unsigned al0 = Xl[r0 * XS + ks + tig];
            unsigned al1 = Xl[(r0 + 8) * XS + ks + tig];
            unsigned al2 = Xl[r0 * XS + ks + tig + 4];
            unsigned al3 = Xl[(r0 + 8) * XS + ks + tig + 4];
#pragma unroll
            for (int nb = 0; nb < 8; ++nb) {
                int col = cgp * 64 + nb * 8 + g;
                unsigned bh0 = Wh[(ks + tig) * WS + col];
                unsigned bh1 = Wh[(ks + tig + 4) * WS + col];
                unsigned bl0 = Wl[(ks + tig) * WS + col];
                unsigned bl1 = Wl[(ks + tig + 4) * WS + col];
                asm volatile(
                    "mma.sync.aligned.m16n8k8.row.col.f32.tf32.tf32.f32 "
                    "{%0,%1,%2,%3}, {%4,%5,%6,%7}, {%8,%9}, {%0,%1,%2,%3};"
                    : "+f"(acc[nb][0]), "+f"(acc[nb][1]), "+f"(acc[nb][2]), "+f"(acc[nb][3])
                    : "r"(ah0), "r"(ah1), "r"(ah2), "r"(ah3), "r"(bh0), "r"(bh1));
                asm volatile(
                    "mma.sync.aligned.m16n8k8.row.col.f32.tf32.tf32.f32 "
                    "{%0,%1,%2,%3}, {%4,%5,%6,%7}, {%8,%9}, {%0,%1,%2,%3};"
                    : "+f"(acc[nb][0]), "+f"(acc[nb][1]), "+f"(acc[nb][2]), "+f"(acc[nb][3])
                    : "r"(ah0), "r"(ah1), "r"(ah2), "r"(ah3), "r"(bl0), "r"(bl1));
                asm volatile(
                    "mma.sync.aligned.m16n8k8.row.col.f32.tf32.tf32.f32 "
                    "{%0,%1,%2,%3}, {%4,%5,%6,%7}, {%8,%9}, {%0,%1,%2,%3};"
                    : "+f"(acc[nb][0]), "+f"(acc[nb][1]), "+f"(acc[nb][2]), "+f"(acc[nb][3])
                    : "r"(al0), "r"(al1), "r"(al2), "r"(al3), "r"(bh0), "r"(bh1));
            }
        }
        __syncthreads();
    }
    int node0 = base + nsub * 16 + g;
#pragma unroll
    for (int nb = 0; nb < 8; ++nb) {
        int col = cgp * 64 + nb * 8 + 2 * tig;
        float b0 = 0.f, b1 = 0.f;
        if (BIAS) { b0 = __ldg(bias + col); b1 = __ldg(bias + col + 1); }
        if (node0 < n) {
            float2 v = make_float2(acc[nb][0] + b0, acc[nb][1] + b1);
            *(float2*)(out + (size_t)node0 * DOUT + col) = v;
        }
        if (node0 + 8 < n) {
            float2 v = make_float2(acc[nb][2] + b0, acc[nb][3] + b1);
            *(float2*)(out + (size_t)(node0 + 8) * DOUT + col) = v;
        }
    }
    if (STATS) {
        __syncthreads();
        int rows = n - base; if (rows > NT) rows = NT;
        constexpr int LPC = 256 / DOUT;
        int col = tid % DOUT, sub = tid / DOUT;
        float s = 0.f, q = 0.f;
        for (int r = sub; r < rows; r += LPC) {
            float v = out[(size_t)(base + r) * DOUT + col];
            s += v; q += v * v;
        }
        __shared__ float red[512];
        red[tid] = s; red[256 + tid] = q;
        __syncthreads();
        if (sub == 0) {
            for (int k = 1; k < LPC; ++k) { s += red[k * DOUT + col]; q += red[256 + k * DOUT + col]; }
            atomicAdd(mean + col, s);
            atomicAdd(sq + col, q);
        }
        __threadfence();
        __shared__ int s_tick;
        if (tid == 0) s_tick = atomicAdd(ticket, 1);
        __syncthreads();
        if (s_tick == gridDim.x - 1) {
            __threadfence();
            if (tid < DOUT) {
                float inv = 1.0f / (float)n;
                float mu = ((volatile float*)mean)[tid] * inv;
                float var = ((volatile float*)sq)[tid] * inv - mu * mu;
                float scv = __ldg(bng + tid) * rsqrtf(var + 1e-5f);
                scale[tid] = scv;
                shift[tid] = __ldg(bnb + tid) - mu * scv;
                mean[tid] = 0.f;
                sq[tid] = 0.f;
            }
            if (tid == 0) *ticket = 0;
        }
    }
    if (SCORES) {
        __syncthreads();
        constexpr int TPN2 = 256 / NT;
        constexpr int HPT = HEADSN / TPN2;
        constexpr int C = DOUT / HEADSN;
        int nodeL = tid / TPN2, part = tid % TPN2;
        int node = base + nodeL;
        if (node < n) {
            const float* row = out + (size_t)node * DOUT;
#pragma unroll
            for (int hh = 0; hh < HPT; ++hh) {
                int head = part * HPT + hh;
                float ps = 0.f, pd = 0.f;
#pragma unroll
                for (int c4 = 0; c4 < C / 4; ++c4) {
                    float4 v = *(const float4*)(row + head * C + c4 * 4);
                    float4 a = __ldg((const float4*)asrc + head * (C / 4) + c4);
                    float4 d = __ldg((const float4*)adst + head * (C / 4) + c4);
                    ps += v.x * a.x + v.y * a.y + v.z * a.z + v.w * a.w;
                    pd += v.x * d.x + v.y * d.y + v.z * d.z + v.w * d.w;
                }
                ssO[(size_t)node * HEADSN + head] = ps;
                sdO[(size_t)node * HEADSN + head] = pd;
            }
        }
    }
}

// ---------------- L3: gather + BN stats + pool, fully fused (no C pass) ----------------
// 16 nodes/block (TPN=16). Gather acc kept in registers; BN stats via smem atomics;
// pool via one float4 global atomic per thread; ticket-final writes output.
__global__ void __launch_bounds__(256)
k_gather_pool(const int* __restrict__ rowptr, const int2* __restrict__ pack,
              const float* __restrict__ dis, const float* __restrict__ h,
              const float* __restrict__ bias, const int* __restrict__ batch,
              float* mean, float* sq,
              const float* __restrict__ bng, const float* __restrict__ bnb,
              float* psum, float* cnt, int* ticket,
              float* __restrict__ outF, int G, int n) {
    constexpr int DOUT = 64;
    constexpr int TPN = 16;
    __shared__ float ssum[DOUT], ssq[DOUT];
    int tid = threadIdx.x;
    if (tid < DOUT) { ssum[tid] = 0.f; ssq[tid] = 0.f; }
    __syncthreads();

    int t = blockIdx.x * 256 + tid;
    int node = t / TPN, sub = t % TPN;
    if (node < n) {
        float dc = __ldg(dis + node);
        float4 acc = __ldg((const float4*)bias + sub);
        {
            float4 v = __ldg((const float4*)h + (size_t)node * TPN + sub);
            float w = dc * dc;
            acc.x += v.x * w; acc.y += v.y * w; acc.z += v.z * w; acc.w += v.w * w;
        }
        int s0 = __ldg(rowptr + node), s1 = __ldg(rowptr + node + 1);
#pragma unroll 4
        for (int j = s0; j < s1; ++j) {
            int2 p = __ldg(pack + j);
            float w = __int_as_float(p.y) * dc;
            float4 v = __ldg((const float4*)h + (size_t)p.x * TPN + sub);
            acc.x += v.x * w; acc.y += v.y * w; acc.z += v.z * w; acc.w += v.w * w;
        }
        // BN stats (smem reduce)
        int col = sub * 4;
        atomicAdd(&ssum[col],     acc.x); atomicAdd(&ssq[col],     acc.x * acc.x);
        atomicAdd(&ssum[col + 1], acc.y); atomicAdd(&ssq[col + 1], acc.y * acc.y);
        atomicAdd(&ssum[col + 2], acc.z); atomicAdd(&ssq[col + 2], acc.z * acc.z);
        atomicAdd(&ssum[col + 3], acc.w); atomicAdd(&ssq[col + 3], acc.w * acc.w);
        // pool (raw sums; affine applied at the end)
        int gg = __ldg(batch + node);
        atomicAdd((float4*)&psum[(size_t)gg * DOUT + col], acc);
        if (sub == 0) atomicAdd(&cnt[gg], 1.0f);
    }
    __syncthreads();
    if (tid < DOUT) {
        atomicAdd(mean + tid, ssum[tid]);
        atomicAdd(sq + tid, ssq[tid]);
    }
    __threadfence();
    __shared__ int s_tick;
    if (tid == 0) s_tick = atomicAdd(ticket, 1);
    __syncthreads();
    if (s_tick == gridDim.x - 1) {
        __threadfence();
        __shared__ float fsc[DOUT], fsh[DOUT];
        if (tid < DOUT) {
            float inv = 1.0f / (float)n;
            float mu = ((volatile float*)mean)[tid] * inv;
            float var = ((volatile float*)sq)[tid] * inv - mu * mu;
            float scv = __ldg(bng + tid) * rsqrtf(var + 1e-5f);
            fsc[tid] = scv;
            fsh[tid] = __ldg(bnb + tid) - mu * scv;
            mean[tid] = 0.f;
            sq[tid] = 0.f;
        }
        __syncthreads();
        for (int i = tid; i < G * DOUT; i += 256) {
            int gg = i / DOUT, c = i % DOUT;
            float cn = fmaxf(((volatile float*)cnt)[gg], 1.0f);
            float raw = ((volatile float*)psum)[i];
            outF[i] = fsc[c] * (raw / cn) + fsh[c];
            psum[i] = 0.f;
        }
        for (int i = tid; i < G; i += 256) cnt[i] = 0.f;
        if (tid == 0) *ticket = 0;
    }
}

// ---------------- L0 gather @ d=16: edge-parallel, warp per node ----------------
__global__ void __launch_bounds__(256)
k_gather16(const int* __restrict__ rowptr, const int2* __restrict__ pack,
           const float* __restrict__ dis, const float* __restrict__ x,
           float* __restrict__ out, int n) {
    int warp = (blockIdx.x * 256 + threadIdx.x) >> 5;
    int lane = threadIdx.x & 31;
    if (warp >= n) return;
    int eg = lane >> 2, sub = lane & 3;
    float dc = __ldg(dis + warp);
    float4 acc = make_float4(0.f, 0.f, 0.f, 0.f);
    int s0 = __ldg(rowptr + warp), s1 = __ldg(rowptr + warp + 1);
    for (int j = s0 + eg; j < s1; j += 8) {
        int2 p = __ldg(pack + j);
        float w = __int_as_float(p.y) * dc;
        float4 v = __ldg((const float4*)x + (size_t)p.x * 4 + sub);
        acc.x += v.x * w; acc.y += v.y * w; acc.z += v.z * w; acc.w += v.w * w;
    }
#pragma unroll
    for (int off = 4; off <= 16; off <<= 1) {
        acc.x += __shfl_xor_sync(0xffffffff, acc.x, off);
        acc.y += __shfl_xor_sync(0xffffffff, acc.y, off);
        acc.z += __shfl_xor_sync(0xffffffff, acc.z, off);
        acc.w += __shfl_xor_sync(0xffffffff, acc.w, off);
    }
    if (eg == 0) {
        float4 v = __ldg((const float4*)x + (size_t)warp * 4 + sub);
        float w = dc * dc;
        acc.x += v.x * w; acc.y += v.y * w; acc.z += v.z * w; acc.w += v.w * w;
        ((float4*)out)[(size_t)warp * 4 + sub] = acc;
    }
}

// ---------------- generic GCN gather (proven R6 shape) ----------------
template <int TPN, bool BIASP, bool AFFINE, bool RELUIN>
__global__ void __launch_bounds__(256)
k_gather(const int* __restrict__ rowptr, const int2* __restrict__ pack,
         const float* __restrict__ dis, const float* __restrict__ h,
         const float* __restrict__ bias,
         const float* __restrict__ sc_, const float* __restrict__ sh_,
         float* __restrict__ out, int n) {
    int t = blockIdx.x * 256 + threadIdx.x;
    int node = t / TPN, sub = t % TPN;
    if (node >= n) return;
    float4 sc, sh;
    if (AFFINE) { sc = __ldg((const float4*)sc_ + sub); sh = __ldg((const float4*)sh_ + sub); }
    float dc = __ldg(dis + node);
    float4 acc = make_float4(0.f, 0.f, 0.f, 0.f);
    if (BIASP) acc = __ldg((const float4*)bias + sub);
    {
        float4 v = __ldg((const float4*)h + (size_t)node * TPN + sub);
        if (AFFINE) {
            v.x = v.x * sc.x + sh.x; v.y = v.y * sc.y + sh.y;
            v.z = v.z * sc.z + sh.z; v.w = v.w * sc.w + sh.w;
        }
        if (RELUIN) { v.x = lrelu(v.x); v.y = lrelu(v.y); v.z = lrelu(v.z); v.w = lrelu(v.w); }
        float w = dc * dc;
        acc.x += v.x * w; acc.y += v.y * w; acc.z += v.z * w; acc.w += v.w * w;
    }
    int s0 = __ldg(rowptr + node), s1 = __ldg(rowptr + node + 1);
#pragma unroll 4
    for (int j = s0; j < s1; ++j) {
        int2 p = __ldg(pack + j);
        float w = __int_as_float(p.y) * dc;
        float4 v = __ldg((const float4*)h + (size_t)p.x * TPN + sub);
        if (AFFINE) {
            v.x = v.x * sc.x + sh.x; v.y = v.y * sc.y + sh.y;
            v.z = v.z * sc.z + sh.z; v.w = v.w * sc.w + sh.w;
        }
        if (RELUIN) { v.x = lrelu(v.x); v.y = lrelu(v.y); v.z = lrelu(v.z); v.w = lrelu(v.w); }
        acc.x += v.x * w; acc.y += v.y * w; acc.z += v.z * w; acc.w += v.w * w;
    }
    ((float4*)out)[(size_t)node * TPN + sub] = acc;
}

// ---------------- GAT: fused ONLINE softmax + weighted gather + residual --------------
template <int TPN, int H, bool RELU>
__global__ void __launch_bounds__(256)
k_gat_fused(const int* __restrict__ rowptr, const int2* __restrict__ pack,
            const float* __restrict__ ss, const float* __restrict__ sd,
            const float* __restrict__ h2, const float* __restrict__ bias,
            const float* __restrict__ resraw,
            const float* __restrict__ sc_, const float* __restrict__ sh_,
            float* __restrict__ out, int n) {
    constexpr int C = TPN * 4 / H;
    int t = blockIdx.x * 256 + threadIdx.x;
    int node = t / TPN, sub = t % TPN;
    if (node >= n) return;
    int head = (sub * 4) / C;
    float sdv = __ldg(sd + (size_t)node * H + head);

    float m = lrelu(__ldg(ss + (size_t)node * H + head) + sdv);
    float wsum = 1.0f;
    float4 acc = __ldg((const float4*)h2 + (size_t)node * TPN + sub);

    int s0 = __ldg(rowptr + node), s1 = __ldg(rowptr + node + 1);
#pragma unroll 4
    for (int j = s0; j < s1; ++j) {
        int r = __ldg(pack + j).x;
        float e = lrelu(__ldg(ss + (size_t)r * H + head) + sdv);
        float4 v = __ldg((const float4*)h2 + (size_t)r * TPN + sub);
        if (e <= m) {
            float w = __expf(e - m);
            wsum += w;
            acc.x += v.x * w; acc.y += v.y * w;
            acc.z += v.z * w; acc.w += v.w * w;
        } else {
            float alpha = __expf(m - e);
            wsum = wsum * alpha + 1.0f;
            acc.x = acc.x * alpha + v.x; acc.y = acc.y * alpha + v.y;
            acc.z = acc.z * alpha + v.z; acc.w = acc.w * alpha + v.w;
            m = e;
        }
    }
    float inv = 1.0f / wsum;
    float4 bv = __ldg((const float4*)bias + sub);
    float4 xr = __ldg((const float4*)resraw + (size_t)node * TPN + sub);
    float4 sc = __ldg((const float4*)sc_ + sub);
    float4 sh = __ldg((const float4*)sh_ + sub);
    float4 o;
    o.x = acc.x * inv + bv.x + (xr.x * sc.x + sh.x);
    o.y = acc.y * inv + bv.y + (xr.y * sc.y + sh.y);
    o.z = acc.z * inv + bv.z + (xr.z * sc.z + sh.z);
    o.w = acc.w * inv + bv.w + (xr.w * sc.w + sh.w);
    if (RELU) { o.x = lrelu(o.x); o.y = lrelu(o.y); o.z = lrelu(o.z); o.w = lrelu(o.w); }
    ((float4*)out)[(size_t)node * TPN + sub] = o;
}

// ---------------- host ----------------
static inline int GRID(long long t) { return (int)((t + 255) / 256); }

extern "C" void kernel_launch(void* const* d_in, const int* in_sizes, int n_in,
                              void* d_out, int out_size) {
    const float* x     = (const float*)d_in[0];
    const int*   ei    = (const int*)d_in[1];
    const int*   batch = (const int*)d_in[2];
    const int n = in_sizes[0] / 16;
    const int E = in_sizes[1] / 2;
    const int* rowp = ei;
    const int* colp = ei + E;

    const float* gcn_w[4] = {(const float*)d_in[3], (const float*)d_in[7],
                             (const float*)d_in[11], (const float*)d_in[15]};
    const float* gcn_b[4] = {(const float*)d_in[4], (const float*)d_in[8],
                             (const float*)d_in[12], (const float*)d_in[16]};
    const float* bn_g[4]  = {(const float*)d_in[5], (const float*)d_in[9],
                             (const float*)d_in[13], (const float*)d_in[17]};
    const float* bn_b[4]  = {(const float*)d_in[6], (const float*)d_in[10],
                             (const float*)d_in[14], (const float*)d_in[18]};
    const float* gat_w0    = (const float*)d_in[19];
    const float* gat_asrc0 = (const float*)d_in[20];
    const float* gat_adst0 = (const float*)d_in[21];
    const float* gat_b0    = (const float*)d_in[22];
    const float* gat_w2    = (const float*)d_in[23];
    const float* gat_asrc2 = (const float*)d_in[24];
    const float* gat_adst2 = (const float*)d_in[25];
    const float* gat_b2    = (const float*)d_in[26];

    float *A, *B, *C, *dis, *ss, *sd, *mean, *sq, *scale, *shift, *psum, *cnt;
    int *deg, *rowptr, *cursor, *blksum, *tick;
    int2* pack;
    cudaGetSymbolAddress((void**)&A, g_A);
    cudaGetSymbolAddress((void**)&B, g_B);
    cudaGetSymbolAddress((void**)&C, g_C);
    cudaGetSymbolAddress((void**)&dis, g_dis);
    cudaGetSymbolAddress((void**)&deg, g_deg);
    cudaGetSymbolAddress((void**)&rowptr, g_rowptr);
    cudaGetSymbolAddress((void**)&cursor, g_cursor);
    cudaGetSymbolAddress((void**)&pack, g_pack);
    cudaGetSymbolAddress((void**)&blksum, g_blksum);
    cudaGetSymbolAddress((void**)&ss, g_ss);
    cudaGetSymbolAddress((void**)&sd, g_sd);
    cudaGetSymbolAddress((void**)&mean, g_mean);
    cudaGetSymbolAddress((void**)&sq, g_sq);
    cudaGetSymbolAddress((void**)&scale, g_scale);
    cudaGetSymbolAddress((void**)&shift, g_shift);
    cudaGetSymbolAddress((void**)&psum, g_psum);
    cudaGetSymbolAddress((void**)&cnt, g_cnt);
    cudaGetSymbolAddress((void**)&tick, g_tick);
    float* out = (float*)d_out;
    const int G = out_size / 64;

    // ---- CSR build: 4 launches, 4 edges/thread in atomic kernels ----
    const int nb = (n + SCAN_CHUNK - 1) / SCAN_CHUNK;
    k_deg_count<<<GRID((E + 3) / 4), 256>>>(colp, deg, E);
    k_scan1<<<nb, SCAN_CHUNK>>>(deg, blksum, n);
    k_scan3_dis<<<nb, SCAN_CHUNK>>>(deg, blksum, rowptr, cursor, dis, n);
    k_csr_fill<<<GRID((E + 3) / 4), 256>>>(rowp, colp, dis, cursor, pack, E);

    // ----- layer 0 -----
    k_gather16<<<(n + 7) / 8, 256>>>(rowptr, pack, dis, x, C, n);
    k_gemm<16, 64, true, false, true, false><<<(n + 127) / 128, 256>>>(
        C, gcn_w[0], gcn_b[0], nullptr, nullptr, B,
        mean, sq, scale, shift, bn_g[0], bn_b[0], tick + 0,
        nullptr, nullptr, nullptr, nullptr, n);
    k_gemm<64, 64, false, true, false, true><<<(n + 127) / 128, 256>>>(
        B, gat_w0, nullptr, scale, shift, A,
        nullptr, nullptr, nullptr, nullptr, nullptr, nullptr, nullptr,
        gat_asrc0, gat_adst0, ss, sd, n);
    k_gat_fused<16, 4, true><<<(n + 15) / 16, 256>>>(
        rowptr, pack, ss, sd, A, gat_b0, B, scale, shift, B, n);

    // ----- layer 1 -----
    k_gather<16, false, false, false><<<(n + 15) / 16, 256>>>(
        rowptr, pack, dis, B, nullptr, nullptr, nullptr, C, n);
    k_gemm<64, 128, true, false, true, false><<<(n + 63) / 64, 256>>>(
        C, gcn_w[1], gcn_b[1], nullptr, nullptr, A,
        mean, sq, scale, shift, bn_g[1], bn_b[1], tick + 1,
        nullptr, nullptr, nullptr, nullptr, n);

    // ----- layer 2 (L1 bn+relu folded into gather input) -----
    k_gather<32, false, true, true><<<(n + 7) / 8, 256>>>(
        rowptr, pack, dis, A, nullptr, scale, shift, C, n);
    k_gemm<128, 128, true, false, true, false><<<(n + 63) / 64, 256>>>(
        C, gcn_w[2], gcn_b[2], nullptr, nullptr, B,
        mean, sq, scale, shift, bn_g[2], bn_b[2], tick + 2,
        nullptr, nullptr, nullptr, nullptr, n);
    k_gemm<128, 128, false, true, false, true><<<(n + 63) / 64, 256>>>(
        B, gat_w2, nullptr, scale, shift, A,
        nullptr, nullptr, nullptr, nullptr, nullptr, nullptr, nullptr,
        gat_asrc2, gat_adst2, ss, sd, n);
    k_gat_fused<32, 4, true><<<(n + 7) / 8, 256>>>(
        rowptr, pack, ss, sd, A, gat_b2, B, scale, shift, B, n);

    // ----- layer 3: gemm, then fused gather + BN stats + pool (no C pass) -----
    k_gemm<128, 64, false, false, false, false><<<(n + 127) / 128, 256>>>(
        B, gcn_w[3], nullptr, nullptr, nullptr, A,
        nullptr, nullptr, nullptr, nullptr, nullptr, nullptr, nullptr,
        nullptr, nullptr, nullptr, nullptr, n);
    k_gather_pool<<<(n + 15) / 16, 256>>>(
        rowptr, pack, dis, A, gcn_b[3], batch,
        mean, sq, bn_g[3], bn_b[3], psum, cnt, tick + 3, out, G, n);
}

// round 14
// speedup vs baseline: 1.0504x; 1.0504x over previous
#include <cuda_runtime.h>
#include <cuda_bf16.h>
#include <math.h>

#define NMAX 100000
#define EMAX 1600000
#define GMAX 256
#define HEADSN 4
#define SCAN_CHUNK 512

// ---------------- scratch ----------------
__device__ __align__(16) float g_A[(size_t)NMAX * 128];
__device__ __align__(16) float g_B[(size_t)NMAX * 128];
__device__ __align__(16) float g_C[(size_t)NMAX * 128];
__device__ __align__(16) float g_dis[NMAX];
__device__ __align__(16) int   g_deg[NMAX];               // zero-init; scan3 self-resets
__device__ __align__(16) int   g_rowptr[NMAX + 1];
__device__ __align__(16) int   g_cursor[NMAX];
__device__ __align__(16) int2  g_pack[EMAX];              // (src, bits(dis[src]))
__device__ __align__(16) int   g_blksum[1024];
__device__ __align__(16) float g_ss[NMAX * HEADSN];
__device__ __align__(16) float g_sd[NMAX * HEADSN];
__device__ __align__(16) float g_mean[128];               // zero-init; final blocks reset
__device__ __align__(16) float g_sq[128];
__device__ __align__(16) float g_scale[128];
__device__ __align__(16) float g_shift[128];
__device__ __align__(16) float g_psum[GMAX * 64];         // raw pool sums; self-reset
__device__ __align__(16) float g_cnt[GMAX];               // self-reset
__device__            int   g_tick[8];                    // zero-init tickets; self-reset

__device__ __forceinline__ float lrelu(float v) { return v > 0.f ? v : 0.2f * v; }
__device__ __forceinline__ unsigned f2tf(float f) {
    unsigned u; asm("cvt.rna.tf32.f32 %0, %1;" : "=r"(u) : "f"(f)); return u;
}

// ---------------- CSR build ----------------
// deg count: 4 edges/thread (measured neutral; fewer blocks)
__global__ void k_deg_count(const int* __restrict__ colp, int* deg, int E) {
    int i0 = (blockIdx.x * blockDim.x + threadIdx.x) * 4;
#pragma unroll
    for (int k = 0; k < 4; ++k) {
        int i = i0 + k;
        if (i < E) atomicAdd(&deg[__ldg(colp + i)], 1);
    }
}
__global__ void k_scan1(const int* __restrict__ deg, int* blksum, int n) {
    __shared__ int sh[SCAN_CHUNK];
    int i = blockIdx.x * SCAN_CHUNK + threadIdx.x;
    sh[threadIdx.x] = (i < n) ? deg[i] : 0;
    __syncthreads();
    for (int off = SCAN_CHUNK / 2; off > 0; off >>= 1) {
        if (threadIdx.x < off) sh[threadIdx.x] += sh[threadIdx.x + off];
        __syncthreads();
    }
    if (threadIdx.x == 0) blksum[blockIdx.x] = sh[0];
}
__global__ void k_scan3_dis(int* __restrict__ deg, const int* __restrict__ blksum,
                            int* rowptr, int* cursor, float* dis, int n) {
    __shared__ int sh[SCAN_CHUNK];
    int tid = threadIdx.x, bid = blockIdx.x;
    int part = 0;
    for (int j = tid; j < bid; j += SCAN_CHUNK) part += __ldg(blksum + j);
    sh[tid] = part;
    __syncthreads();
    for (int off = SCAN_CHUNK / 2; off > 0; off >>= 1) {
        if (tid < off) sh[tid] += sh[tid + off];
        __syncthreads();
    }
    int base = sh[0];
    __syncthreads();
    int i = bid * SCAN_CHUNK + tid;
    int v = (i < n) ? deg[i] : 0;
    sh[tid] = v;
    __syncthreads();
    for (int off = 1; off < SCAN_CHUNK; off <<= 1) {
        int t = (tid >= off) ? sh[tid - off] : 0;
        __syncthreads();
        sh[tid] += t;
        __syncthreads();
    }
    if (i < n) {
        int excl = base + sh[tid] - v;
        rowptr[i] = excl;
        cursor[i] = excl;
        dis[i] = rsqrtf(1.0f + (float)v);
        if (i == n - 1) rowptr[n] = excl + v;
        deg[i] = 0;   // reset for next replay (deterministic)
    }
}
__global__ void k_csr_fill(const int* __restrict__ rowp, const int* __restrict__ colp,
                           const float* __restrict__ dis, int* cursor, int2* pack, int E) {
    int e = blockIdx.x * blockDim.x + threadIdx.x;
    if (e >= E) return;
    int c = colp[e];
    int r = rowp[e];
    int pos = atomicAdd(&cursor[c], 1);
    pack[pos] = make_int2(r, __float_as_int(__ldg(dis + r)));
}

// ---------------- split-TF32 GEMM (+ fused BN stats / GAT scores epilogues) ------------
template <int DIN, int DOUT, bool BIAS, bool AFFINE, bool STATS, bool SCORES>
__global__ void k_gemm(const float* __restrict__ X, const float* __restrict__ W,
                       const float* __restrict__ bias,
                       const float* __restrict__ sc_, const float* __restrict__ sh_,
                       float* __restrict__ out,
                       float* mean, float* sq, float* scale, float* shift,
                       const float* __restrict__ bng, const float* __restrict__ bnb,
                       int* ticket,
                       const float* __restrict__ asrc, const float* __restrict__ adst,
                       float* __restrict__ ssO, float* __restrict__ sdO, int n) {
    constexpr int NT = (DOUT >= 128) ? 64 : 128;
    constexpr int KT = (DIN < 32) ? DIN : 32;
    constexpr int NW = NT / 16;
    constexpr int XS = KT + 4;
    constexpr int WS = DOUT + 4;
    __shared__ unsigned Xh[NT * XS];
    __shared__ unsigned Xl[NT * XS];
    __shared__ unsigned Wh[KT * WS];
    __shared__ unsigned Wl[KT * WS];

    const int tid = threadIdx.x;
    const int wid = tid >> 5, lane = tid & 31;
    const int g = lane >> 2, tig = lane & 3;
    const int nsub = wid % NW, cgp = wid / NW;
    const int base = blockIdx.x * NT;

    float acc[8][4];
#pragma unroll
    for (int i = 0; i < 8; ++i)
#pragma unroll
        for (int j = 0; j < 4; ++j) acc[i][j] = 0.f;

    for (int kt = 0; kt < DIN; kt += KT) {
        for (int i = tid; i < NT * (KT / 4); i += 256) {
            int r = i / (KT / 4), c = i % (KT / 4);
            int node = base + r;
            float4 v = make_float4(0.f, 0.f, 0.f, 0.f);
            if (node < n) v = ((const float4*)X)[(size_t)node * (DIN / 4) + kt / 4 + c];
            if (AFFINE) {
                float4 sc = __ldg((const float4*)sc_ + kt / 4 + c);
                float4 sh = __ldg((const float4*)sh_ + kt / 4 + c);
                v.x = v.x * sc.x + sh.x; v.y = v.y * sc.y + sh.y;
                v.z = v.z * sc.z + sh.z; v.w = v.w * sc.w + sh.w;
            }
            unsigned* dh = &Xh[r * XS + c * 4];
            unsigned* dl = &Xl[r * XS + c * 4];
            unsigned h0 = f2tf(v.x), h1 = f2tf(v.y), h2 = f2tf(v.z), h3 = f2tf(v.w);
            dh[0] = h0; dh[1] = h1; dh[2] = h2; dh[3] = h3;
            dl[0] = f2tf(v.x - __uint_as_float(h0));
            dl[1] = f2tf(v.y - __uint_as_float(h1));
            dl[2] = f2tf(v.z - __uint_as_float(h2));
            dl[3] = f2tf(v.w - __uint_as_float(h3));
        }
        for (int i = tid; i < KT * (DOUT / 4); i += 256) {
            int r = i / (DOUT / 4), c = i % (DOUT / 4);
            float4 v = ((const float4*)W)[(size_t)(kt + r) * (DOUT / 4) + c];
            unsigned* dh = &Wh[r * WS + c * 4];
            unsigned* dl = &Wl[r * WS + c * 4];
            unsigned h0 = f2tf(v.x), h1 = f2tf(v.y), h2 = f2tf(v.z), h3 = f2tf(v.w);
            dh[0] = h0; dh[1] = h1; dh[2] = h2; dh[3] = h3;
            dl[0] = f2tf(v.x - __uint_as_float(h0));
            dl[1] = f2tf(v.y - __uint_as_float(h1));
            dl[2] = f2tf(v.z - __uint_as_float(h2));
            dl[3] = f2tf(v.w - __uint_as_float(h3));
        }
        __syncthreads();
#pragma unroll
        for (int ks = 0; ks < KT; ks += 8) {
            int r0 = nsub * 16 + g;
            unsigned ah0 = Xh[r0 * XS + ks + tig];
            unsigned ah1 = Xh[(r0 + 8) * XS + ks + tig];
            unsigned ah2 = Xh[r0 * XS + ks + tig + 4];
            unsigned ah3 = Xh[(r0 + 8) * XS + ks + tig + 4];
            unsigned al0 = Xl[r0 * XS + ks + tig];
            unsigned al1 = Xl[(r0 + 8) * XS + ks + tig];
            unsigned al2 = Xl[r0 * XS + ks + tig + 4];
            unsigned al3 = Xl[(r0 + 8) * XS + ks + tig + 4];
#pragma unroll
            for (int nb = 0; nb < 8; ++nb) {
                int col = cgp * 64 + nb * 8 + g;
                unsigned bh0 = Wh[(ks + tig) * WS + col];
                unsigned bh1 = Wh[(ks + tig + 4) * WS + col];
                unsigned bl0 = Wl[(ks + tig) * WS + col];
                unsigned bl1 = Wl[(ks + tig + 4) * WS + col];
                asm volatile(
                    "mma.sync.aligned.m16n8k8.row.col.f32.tf32.tf32.f32 "
                    "{%0,%1,%2,%3}, {%4,%5,%6,%7}, {%8,%9}, {%0,%1,%2,%3};"
                    : "+f"(acc[nb][0]), "+f"(acc[nb][1]), "+f"(acc[nb][2]), "+f"(acc[nb][3])
                    : "r"(ah0), "r"(ah1), "r"(ah2), "r"(ah3), "r"(bh0), "r"(bh1));
                asm volatile(
                    "mma.sync.aligned.m16n8k8.row.col.f32.tf32.tf32.f32 "
                    "{%0,%1,%2,%3}, {%4,%5,%6,%7}, {%8,%9}, {%0,%1,%2,%3};"
                    : "+f"(acc[nb][0]), "+f"(acc[nb][1]), "+f"(acc[nb][2]), "+f"(acc[nb][3])
                    : "r"(ah0), "r"(ah1), "r"(ah2), "r"(ah3), "r"(bl0), "r"(bl1));
                asm volatile(
                    "mma.sync.aligned.m16n8k8.row.col.f32.tf32.tf32.f32 "
                    "{%0,%1,%2,%3}, {%4,%5,%6,%7}, {%8,%9}, {%0,%1,%2,%3};"
                    : "+f"(acc[nb][0]), "+f"(acc[nb][1]), "+f"(acc[nb][2]), "+f"(acc[nb][3])
                    : "r"(al0), "r"(al1), "r"(al2), "r"(al3), "r"(bh0), "r"(bh1));
            }
        }
        __syncthreads();
    }
    int node0 = base + nsub * 16 + g;
#pragma unroll
    for (int nb = 0; nb < 8; ++nb) {
        int col = cgp * 64 + nb * 8 + 2 * tig;
        float b0 = 0.f, b1 = 0.f;
        if (BIAS) { b0 = __ldg(bias + col); b1 = __ldg(bias + col + 1); }
        if (node0 < n) {
            float2 v = make_float2(acc[nb][0] + b0, acc[nb][1] + b1);
            *(float2*)(out + (size_t)node0 * DOUT + col) = v;
        }
        if (node0 + 8 < n) {
            float2 v = make_float2(acc[nb][2] + b0, acc[nb][3] + b1);
            *(float2*)(out + (size_t)(node0 + 8) * DOUT + col) = v;
        }
    }
    if (STATS) {
        __syncthreads();
        int rows = n - base; if (rows > NT) rows = NT;
        constexpr int LPC = 256 / DOUT;
        int col = tid % DOUT, sub = tid / DOUT;
        float s = 0.f, q = 0.f;
        for (int r = sub; r < rows; r += LPC) {
            float v = out[(size_t)(base + r) * DOUT + col];
            s += v; q += v * v;
        }
        __shared__ float red[512];
        red[tid] = s; red[256 + tid] = q;
        __syncthreads();
        if (sub == 0) {
            for (int k = 1; k < LPC; ++k) { s += red[k * DOUT + col]; q += red[256 + k * DOUT + col]; }
            atomicAdd(mean + col, s);
            atomicAdd(sq + col, q);
        }
        __threadfence();
        __shared__ int s_tick;
        if (tid == 0) s_tick = atomicAdd(ticket, 1);
        __syncthreads();
        if (s_tick == gridDim.x - 1) {
            __threadfence();
            if (tid < DOUT) {
                float inv = 1.0f / (float)n;
                float mu = ((volatile float*)mean)[tid] * inv;
                float var = ((volatile float*)sq)[tid] * inv - mu * mu;
                float scv = __ldg(bng + tid) * rsqrtf(var + 1e-5f);
                scale[tid] = scv;
                shift[tid] = __ldg(bnb + tid) - mu * scv;
                mean[tid] = 0.f;
                sq[tid] = 0.f;
            }
            if (tid == 0) *ticket = 0;
        }
    }
    if (SCORES) {
        __syncthreads();
        constexpr int TPN2 = 256 / NT;
        constexpr int HPT = HEADSN / TPN2;
        constexpr int C = DOUT / HEADSN;
        int nodeL = tid / TPN2, part = tid % TPN2;
        int node = base + nodeL;
        if (node < n) {
            const float* row = out + (size_t)node * DOUT;
#pragma unroll
            for (int hh = 0; hh < HPT; ++hh) {
                int head = part * HPT + hh;
                float ps = 0.f, pd = 0.f;
#pragma unroll
                for (int c4 = 0; c4 < C / 4; ++c4) {
                    float4 v = *(const float4*)(row + head * C + c4 * 4);
                    float4 a = __ldg((const float4*)asrc + head * (C / 4) + c4);
                    float4 d = __ldg((const float4*)adst + head * (C / 4) + c4);
                    ps += v.x * a.x + v.y * a.y + v.z * a.z + v.w * a.w;
                    pd += v.x * d.x + v.y * d.y + v.z * d.z + v.w * d.w;
                }
                ssO[(size_t)node * HEADSN + head] = ps;
                sdO[(size_t)node * HEADSN + head] = pd;
            }
        }
    }
}

// ---------------- L3: BN stats + raw mean-pool in ONE pass; ticket-final writes out ----
__global__ void k_bn_pool(const float* __restrict__ src, const int* __restrict__ batch,
                          float* mean, float* sq,
                          const float* __restrict__ bng, const float* __restrict__ bnb,
                          float* psum, float* cnt, int* ticket,
                          float* __restrict__ outF, int G, int n) {
    constexpr int DOUT = 64;
    constexpr int LPC = 4;   // 256/64
    constexpr int NPB = 64;
    int tid = threadIdx.x;
    int col = tid % DOUT, sub = tid / DOUT;
    int base = blockIdx.x * NPB;
    int end = base + NPB; if (end > n) end = n;
    float s = 0.f, q = 0.f;
    float ps = 0.f; int curg = -1; float pc = 0.f;
    for (int nn = base + sub; nn < end; nn += LPC) {
        float v = src[(size_t)nn * DOUT + col];
        s += v; q += v * v;
        int gg = __ldg(batch + nn);
        if (gg != curg) {
            if (curg >= 0) {
                atomicAdd(&psum[(size_t)curg * DOUT + col], ps);
                if (col == 0) atomicAdd(&cnt[curg], pc);
            }
            ps = 0.f; pc = 0.f; curg = gg;
        }
        ps += v; pc += 1.f;
    }
    if (curg >= 0) {
        atomicAdd(&psum[(size_t)curg * DOUT + col], ps);
        if (col == 0) atomicAdd(&cnt[curg], pc);
    }
    __shared__ float sh[512];
    sh[tid] = s; sh[256 + tid] = q;
    __syncthreads();
    if (sub == 0) {
        for (int k = 1; k < LPC; ++k) { s += sh[k * DOUT + col]; q += sh[256 + k * DOUT + col]; }
        atomicAdd(mean + col, s);
        atomicAdd(sq + col, q);
    }
    __threadfence();
    __shared__ int s_tick;
    if (tid == 0) s_tick = atomicAdd(ticket, 1);
    __syncthreads();
    if (s_tick == gridDim.x - 1) {
        __threadfence();
        __shared__ float ssc[DOUT], ssh[DOUT];
        if (tid < DOUT) {
            float inv = 1.0f / (float)n;
            float mu = ((volatile float*)mean)[tid] * inv;
            float var = ((volatile float*)sq)[tid] * inv - mu * mu;
            float scv = __ldg(bng + tid) * rsqrtf(var + 1e-5f);
            ssc[tid] = scv;
            ssh[tid] = __ldg(bnb + tid) - mu * scv;
            mean[tid] = 0.f;
            sq[tid] = 0.f;
        }
        __syncthreads();
        for (int i = tid; i < G * DOUT; i += 256) {
            int gg = i / DOUT, c = i % DOUT;
            float cn = fmaxf(((volatile float*)cnt)[gg], 1.0f);
            float raw = ((volatile float*)psum)[i];
            outF[i] = ssc[c] * (raw / cn) + ssh[c];
            psum[i] = 0.f;
        }
        for (int i = tid; i < G; i += 256) cnt[i] = 0.f;
        if (tid == 0) *ticket = 0;
    }
}

// ---------------- L0 gather @ d=16: edge-parallel, warp per node ----------------
__global__ void __launch_bounds__(256)
k_gather16(const int* __restrict__ rowptr, const int2* __restrict__ pack,
           const float* __restrict__ dis, const float* __restrict__ x,
           float* __restrict__ out, int n) {
    int warp = (blockIdx.x * 256 + threadIdx.x) >> 5;
    int lane = threadIdx.x & 31;
    if (warp >= n) return;
    int eg = lane >> 2, sub = lane & 3;
    float dc = __ldg(dis + warp);
    float4 acc = make_float4(0.f, 0.f, 0.f, 0.f);
    int s0 = __ldg(rowptr + warp), s1 = __ldg(rowptr + warp + 1);
    for (int j = s0 + eg; j < s1; j += 8) {
        int2 p = __ldg(pack + j);
        float w = __int_as_float(p.y) * dc;
        float4 v = __ldg((const float4*)x + (size_t)p.x * 4 + sub);
        acc.x += v.x * w; acc.y += v.y * w; acc.z += v.z * w; acc.w += v.w * w;
    }
#pragma unroll
    for (int off = 4; off <= 16; off <<= 1) {
        acc.x += __shfl_xor_sync(0xffffffff, acc.x, off);
        acc.y += __shfl_xor_sync(0xffffffff, acc.y, off);
        acc.z += __shfl_xor_sync(0xffffffff, acc.z, off);
        acc.w += __shfl_xor_sync(0xffffffff, acc.w, off);
    }
    if (eg == 0) {
        float4 v = __ldg((const float4*)x + (size_t)warp * 4 + sub);
        float w = dc * dc;
        acc.x += v.x * w; acc.y += v.y * w; acc.z += v.z * w; acc.w += v.w * w;
        ((float4*)out)[(size_t)warp * 4 + sub] = acc;
    }
}

// ---------------- generic GCN gather (proven R6 shape) ----------------
template <int TPN, bool BIASP, bool AFFINE, bool RELUIN>
__global__ void __launch_bounds__(256)
k_gather(const int* __restrict__ rowptr, const int2* __restrict__ pack,
         const float* __restrict__ dis, const float* __restrict__ h,
         const float* __restrict__ bias,
         const float* __restrict__ sc_, const float* __restrict__ sh_,
         float* __restrict__ out, int n) {
    int t = blockIdx.x * 256 + threadIdx.x;
    int node = t / TPN, sub = t % TPN;
    if (node >= n) return;
    float4 sc, sh;
    if (AFFINE) { sc = __ldg((const float4*)sc_ + sub); sh = __ldg((const float4*)sh_ + sub); }
    float dc = __ldg(dis + node);
    float4 acc = make_float4(0.f, 0.f, 0.f, 0.f);
    if (BIASP) acc = __ldg((const float4*)bias + sub);
    {
        float4 v = __ldg((const float4*)h + (size_t)node * TPN + sub);
        if (AFFINE) {
            v.x = v.x * sc.x + sh.x; v.y = v.y * sc.y + sh.y;
            v.z = v.z * sc.z + sh.z; v.w = v.w * sc.w + sh.w;
        }
        if (RELUIN) { v.x = lrelu(v.x); v.y = lrelu(v.y); v.z = lrelu(v.z); v.w = lrelu(v.w); }
        float w = dc * dc;
        acc.x += v.x * w; acc.y += v.y * w; acc.z += v.z * w; acc.w += v.w * w;
    }
    int s0 = __ldg(rowptr + node), s1 = __ldg(rowptr + node + 1);
#pragma unroll 4
    for (int j = s0; j < s1; ++j) {
        int2 p = __ldg(pack + j);
        float w = __int_as_float(p.y) * dc;
        float4 v = __ldg((const float4*)h + (size_t)p.x * TPN + sub);
        if (AFFINE) {
            v.x = v.x * sc.x + sh.x; v.y = v.y * sc.y + sh.y;
            v.z = v.z * sc.z + sh.z; v.w = v.w * sc.w + sh.w;
        }
        if (RELUIN) { v.x = lrelu(v.x); v.y = lrelu(v.y); v.z = lrelu(v.z); v.w = lrelu(v.w); }
        acc.x += v.x * w; acc.y += v.y * w; acc.z += v.z * w; acc.w += v.w * w;
    }
    ((float4*)out)[(size_t)node * TPN + sub] = acc;
}

// ---------------- GAT: fused ONLINE softmax + weighted gather + residual --------------
template <int TPN, int H, bool RELU>
__global__ void __launch_bounds__(256)
k_gat_fused(const int* __restrict__ rowptr, const int2* __restrict__ pack,
            const float* __restrict__ ss, const float* __restrict__ sd,
            const float* __restrict__ h2, const float* __restrict__ bias,
            const float* __restrict__ resraw,
            const float* __restrict__ sc_, const float* __restrict__ sh_,
            float* __restrict__ out, int n) {
    constexpr int C = TPN * 4 / H;
    int t = blockIdx.x * 256 + threadIdx.x;
    int node = t / TPN, sub = t % TPN;
    if (node >= n) return;
    int head = (sub * 4) / C;
    float sdv = __ldg(sd + (size_t)node * H + head);

    float m = lrelu(__ldg(ss + (size_t)node * H + head) + sdv);
    float wsum = 1.0f;
    float4 acc = __ldg((const float4*)h2 + (size_t)node * TPN + sub);

    int s0 = __ldg(rowptr + node), s1 = __ldg(rowptr + node + 1);
#pragma unroll 4
    for (int j = s0; j < s1; ++j) {
        int r = __ldg(pack + j).x;
        float e = lrelu(__ldg(ss + (size_t)r * H + head) + sdv);
        float4 v = __ldg((const float4*)h2 + (size_t)r * TPN + sub);
        if (e <= m) {
            float w = __expf(e - m);
            wsum += w;
            acc.x += v.x * w; acc.y += v.y * w;
            acc.z += v.z * w; acc.w += v.w * w;
        } else {
            float alpha = __expf(m - e);
            wsum = wsum * alpha + 1.0f;
            acc.x = acc.x * alpha + v.x; acc.y = acc.y * alpha + v.y;
            acc.z = acc.z * alpha + v.z; acc.w = acc.w * alpha + v.w;
            m = e;
        }
    }
    float inv = 1.0f / wsum;
    float4 bv = __ldg((const float4*)bias + sub);
    float4 xr = __ldg((const float4*)resraw + (size_t)node * TPN + sub);
    float4 sc = __ldg((const float4*)sc_ + sub);
    float4 sh = __ldg((const float4*)sh_ + sub);
    float4 o;
    o.x = acc.x * inv + bv.x + (xr.x * sc.x + sh.x);
    o.y = acc.y * inv + bv.y + (xr.y * sc.y + sh.y);
    o.z = acc.z * inv + bv.z + (xr.z * sc.z + sh.z);
    o.w = acc.w * inv + bv.w + (xr.w * sc.w + sh.w);
    if (RELU) { o.x = lrelu(o.x); o.y = lrelu(o.y); o.z = lrelu(o.z); o.w = lrelu(o.w); }
    ((float4*)out)[(size_t)node * TPN + sub] = o;
}

// ---------------- host ----------------
static inline int GRID(long long t) { return (int)((t + 255) / 256); }

extern "C" void kernel_launch(void* const* d_in, const int* in_sizes, int n_in,
                              void* d_out, int out_size) {
    const float* x     = (const float*)d_in[0];
    const int*   ei    = (const int*)d_in[1];
    const int*   batch = (const int*)d_in[2];
    const int n = in_sizes[0] / 16;
    const int E = in_sizes[1] / 2;
    const int* rowp = ei;
    const int* colp = ei + E;

    const float* gcn_w[4] = {(const float*)d_in[3], (const float*)d_in[7],
                             (const float*)d_in[11], (const float*)d_in[15]};
    const float* gcn_b[4] = {(const float*)d_in[4], (const float*)d_in[8],
                             (const float*)d_in[12], (const float*)d_in[16]};
    const float* bn_g[4]  = {(const float*)d_in[5], (const float*)d_in[9],
                             (const float*)d_in[13], (const float*)d_in[17]};
    const float* bn_b[4]  = {(const float*)d_in[6], (const float*)d_in[10],
                             (const float*)d_in[14], (const float*)d_in[18]};
    const float* gat_w0    = (const float*)d_in[19];
    const float* gat_asrc0 = (const float*)d_in[20];
    const float* gat_adst0 = (const float*)d_in[21];
    const float* gat_b0    = (const float*)d_in[22];
    const float* gat_w2    = (const float*)d_in[23];
    const float* gat_asrc2 = (const float*)d_in[24];
    const float* gat_adst2 = (const float*)d_in[25];
    const float* gat_b2    = (const float*)d_in[26];

    float *A, *B, *C, *dis, *ss, *sd, *mean, *sq, *scale, *shift, *psum, *cnt;
    int *deg, *rowptr, *cursor, *blksum, *tick;
    int2* pack;
    cudaGetSymbolAddress((void**)&A, g_A);
    cudaGetSymbolAddress((void**)&B, g_B);
    cudaGetSymbolAddress((void**)&C, g_C);
    cudaGetSymbolAddress((void**)&dis, g_dis);
    cudaGetSymbolAddress((void**)&deg, g_deg);
    cudaGetSymbolAddress((void**)&rowptr, g_rowptr);
    cudaGetSymbolAddress((void**)&cursor, g_cursor);
    cudaGetSymbolAddress((void**)&pack, g_pack);
    cudaGetSymbolAddress((void**)&blksum, g_blksum);
    cudaGetSymbolAddress((void**)&ss, g_ss);
    cudaGetSymbolAddress((void**)&sd, g_sd);
    cudaGetSymbolAddress((void**)&mean, g_mean);
    cudaGetSymbolAddress((void**)&sq, g_sq);
    cudaGetSymbolAddress((void**)&scale, g_scale);
    cudaGetSymbolAddress((void**)&shift, g_shift);
    cudaGetSymbolAddress((void**)&psum, g_psum);
    cudaGetSymbolAddress((void**)&cnt, g_cnt);
    cudaGetSymbolAddress((void**)&tick, g_tick);
    float* out = (float*)d_out;
    const int G = out_size / 64;

    // ---- CSR build: 4 launches ----
    const int nb = (n + SCAN_CHUNK - 1) / SCAN_CHUNK;
    k_deg_count<<<GRID((E + 3) / 4), 256>>>(colp, deg, E);
    k_scan1<<<nb, SCAN_CHUNK>>>(deg, blksum, n);
    k_scan3_dis<<<nb, SCAN_CHUNK>>>(deg, blksum, rowptr, cursor, dis, n);
    k_csr_fill<<<GRID(E), 256>>>(rowp, colp, dis, cursor, pack, E);

    // ----- layer 0 -----
    k_gather16<<<(n + 7) / 8, 256>>>(rowptr, pack, dis, x, C, n);
    k_gemm<16, 64, true, false, true, false><<<(n + 127) / 128, 256>>>(
        C, gcn_w[0], gcn_b[0], nullptr, nullptr, B,
        mean, sq, scale, shift, bn_g[0], bn_b[0], tick + 0,
        nullptr, nullptr, nullptr, nullptr, n);
    k_gemm<64, 64, false, true, false, true><<<(n + 127) / 128, 256>>>(
        B, gat_w0, nullptr, scale, shift, A,
        nullptr, nullptr, nullptr, nullptr, nullptr, nullptr, nullptr,
        gat_asrc0, gat_adst0, ss, sd, n);
    k_gat_fused<16, 4, true><<<(n + 15) / 16, 256>>>(
        rowptr, pack, ss, sd, A, gat_b0, B, scale, shift, B, n);

    // ----- layer 1 -----
    k_gather<16, false, false, false><<<(n + 15) / 16, 256>>>(
        rowptr, pack, dis, B, nullptr, nullptr, nullptr, C, n);
    k_gemm<64, 128, true, false, true, false><<<(n + 63) / 64, 256>>>(
        C, gcn_w[1], gcn_b[1], nullptr, nullptr, A,
        mean, sq, scale, shift, bn_g[1], bn_b[1], tick + 1,
        nullptr, nullptr, nullptr, nullptr, n);

    // ----- layer 2 (L1 bn+relu folded into gather input) -----
    k_gather<32, false, true, true><<<(n + 7) / 8, 256>>>(
        rowptr, pack, dis, A, nullptr, scale, shift, C, n);
    k_gemm<128, 128, true, false, true, false><<<(n + 63) / 64, 256>>>(
        C, gcn_w[2], gcn_b[2], nullptr, nullptr, B,
        mean, sq, scale, shift, bn_g[2], bn_b[2], tick + 2,
        nullptr, nullptr, nullptr, nullptr, n);
    k_gemm<128, 128, false, true, false, true><<<(n + 63) / 64, 256>>>(
        B, gat_w2, nullptr, scale, shift, A,
        nullptr, nullptr, nullptr, nullptr, nullptr, nullptr, nullptr,
        gat_asrc2, gat_adst2, ss, sd, n);
    k_gat_fused<32, 4, true><<<(n + 7) / 8, 256>>>(
        rowptr, pack, ss, sd, A, gat_b2, B, scale, shift, B, n);

    // ----- layer 3: gemm, gather(+bias), fused BN-stats + mean-pool -----
    k_gemm<128, 64, false, false, false, false><<<(n + 127) / 128, 256>>>(
        B, gcn_w[3], nullptr, nullptr, nullptr, A,
        nullptr, nullptr, nullptr, nullptr, nullptr, nullptr, nullptr,
        nullptr, nullptr, nullptr, nullptr, n);
    k_gather<16, true, false, false><<<(n + 15) / 16, 256>>>(
        rowptr, pack, dis, A, gcn_b[3], nullptr, nullptr, C, n);
    k_bn_pool<<<(n + 63) / 64, 256>>>(
        C, batch, mean, sq, bn_g[3], bn_b[3], psum, cnt, tick + 3, out, G, n);
}

// round 15
// speedup vs baseline: 1.0888x; 1.0366x over previous
#include <cuda_runtime.h>
#include <cuda_bf16.h>
#include <math.h>

#define NMAX 100000
#define EMAX 1600000
#define GMAX 256
#define HEADSN 4
#define SCAN_CHUNK 512

// ---------------- scratch ----------------
__device__ __align__(16) float g_A[(size_t)NMAX * 128];
__device__ __align__(16) float g_B[(size_t)NMAX * 128];
__device__ __align__(16) float g_C[(size_t)NMAX * 128];
__device__ __align__(16) float g_dis[NMAX];
__device__ __align__(16) int   g_deg[NMAX];               // zero-init; csr_fill self-resets
__device__ __align__(16) int   g_rowptr[NMAX + 1];
__device__ __align__(16) int   g_cursor[NMAX];
__device__ __align__(16) int2  g_pack[EMAX];              // (src, bits(dis[src]))
__device__ __align__(16) float g_ss[NMAX * HEADSN];
__device__ __align__(16) float g_sd[NMAX * HEADSN];
__device__ __align__(16) float g_mean[128];               // zero-init; final blocks reset
__device__ __align__(16) float g_sq[128];
__device__ __align__(16) float g_scale[128];
__device__ __align__(16) float g_shift[128];
__device__ __align__(16) float g_psum[GMAX * 64];         // raw pool sums; self-reset
__device__ __align__(16) float g_cnt[GMAX];               // self-reset
__device__            int   g_tick[8];                    // zero-init tickets; self-reset

__device__ __forceinline__ float lrelu(float v) { return v > 0.f ? v : 0.2f * v; }
__device__ __forceinline__ unsigned f2tf(float f) {
    unsigned u; asm("cvt.rna.tf32.f32 %0, %1;" : "=r"(u) : "f"(f)); return u;
}

// ---------------- CSR build ----------------
__global__ void k_deg_count(const int* __restrict__ colp, int* deg, int E) {
    int i0 = (blockIdx.x * blockDim.x + threadIdx.x) * 4;
#pragma unroll
    for (int k = 0; k < 4; ++k) {
        int i = i0 + k;
        if (i < E) atomicAdd(&deg[__ldg(colp + i)], 1);
    }
}
// single-pass scan: each block sums deg[0..chunk_start) directly, then scans its chunk.
// deg is NOT reset here (other blocks still read it) — csr_fill resets it.
__global__ void k_scan_dis(const int* __restrict__ deg,
                           int* rowptr, int* cursor, float* dis, int n) {
    __shared__ int sh[SCAN_CHUNK];
    int tid = threadIdx.x, bid = blockIdx.x;
    int limit = bid * SCAN_CHUNK;
    int part = 0;
    for (int j = tid; j < limit; j += SCAN_CHUNK) part += __ldg(deg + j);
    sh[tid] = part;
    __syncthreads();
    for (int off = SCAN_CHUNK / 2; off > 0; off >>= 1) {
        if (tid < off) sh[tid] += sh[tid + off];
        __syncthreads();
    }
    int base = sh[0];
    __syncthreads();
    int i = limit + tid;
    int v = (i < n) ? __ldg(deg + i) : 0;
    sh[tid] = v;
    __syncthreads();
    for (int off = 1; off < SCAN_CHUNK; off <<= 1) {
        int t = (tid >= off) ? sh[tid - off] : 0;
        __syncthreads();
        sh[tid] += t;
        __syncthreads();
    }
    if (i < n) {
        int excl = base + sh[tid] - v;
        rowptr[i] = excl;
        cursor[i] = excl;
        dis[i] = rsqrtf(1.0f + (float)v);
        if (i == n - 1) rowptr[n] = excl + v;
    }
}
// fill packed CSR; also resets deg for next replay (doesn't read deg)
__global__ void k_csr_fill(const int* __restrict__ rowp, const int* __restrict__ colp,
                           const float* __restrict__ dis, int* cursor, int2* pack,
                           int* deg, int E, int n) {
    int e = blockIdx.x * blockDim.x + threadIdx.x;
    if (e < n) deg[e] = 0;
    if (e >= E) return;
    int c = colp[e];
    int r = rowp[e];
    int pos = atomicAdd(&cursor[c], 1);
    pack[pos] = make_int2(r, __float_as_int(__ldg(dis + r)));
}

// ---------------- split-TF32 GEMM (+ fused BN stats / GAT scores epilogues) ------------
template <int DIN, int DOUT, bool BIAS, bool AFFINE, bool STATS, bool SCORES>
__global__ void k_gemm(const float* __restrict__ X, const float* __restrict__ W,
                       const float* __restrict__ bias,
                       const float* __restrict__ sc_, const float* __restrict__ sh_,
                       float* __restrict__ out,
                       float* mean, float* sq, float* scale, float* shift,
                       const float* __restrict__ bng, const float* __restrict__ bnb,
                       int* ticket,
                       const float* __restrict__ asrc, const float* __restrict__ adst,
                       float* __restrict__ ssO, float* __restrict__ sdO, int n) {
    constexpr int NT = (DOUT >= 128) ? 64 : 128;
    constexpr int KT = (DIN < 32) ? DIN : 32;
    constexpr int NW = NT / 16;
    constexpr int XS = KT + 4;
    constexpr int WS = DOUT + 4;
    __shared__ unsigned Xh[NT * XS];
    __shared__ unsigned Xl[NT * XS];
    __shared__ unsigned Wh[KT * WS];
    __shared__ unsigned Wl[KT * WS];

    const int tid = threadIdx.x;
    const int wid = tid >> 5, lane = tid & 31;
    const int g = lane >> 2, tig = lane & 3;
    const int nsub = wid % NW, cgp = wid / NW;
    const int base = blockIdx.x * NT;

    float acc[8][4];
#pragma unroll
    for (int i = 0; i < 8; ++i)
#pragma unroll
        for (int j = 0; j < 4; ++j) acc[i][j] = 0.f;

    for (int kt = 0; kt < DIN; kt += KT) {
        for (int i = tid; i < NT * (KT / 4); i += 256) {
            int r = i / (KT / 4), c = i % (KT / 4);
            int node = base + r;
            float4 v = make_float4(0.f, 0.f, 0.f, 0.f);
            if (node < n) v = ((const float4*)X)[(size_t)node * (DIN / 4) + kt / 4 + c];
            if (AFFINE) {
                float4 sc = __ldg((const float4*)sc_ + kt / 4 + c);
                float4 sh = __ldg((const float4*)sh_ + kt / 4 + c);
                v.x = v.x * sc.x + sh.x; v.y = v.y * sc.y + sh.y;
                v.z = v.z * sc.z + sh.z; v.w = v.w * sc.w + sh.w;
            }
            unsigned* dh = &Xh[r * XS + c * 4];
            unsigned* dl = &Xl[r * XS + c * 4];
            unsigned h0 = f2tf(v.x), h1 = f2tf(v.y), h2 = f2tf(v.z), h3 = f2tf(v.w);
            dh[0] = h0; dh[1] = h1; dh[2] = h2; dh[3] = h3;
            dl[0] = f2tf(v.x - __uint_as_float(h0));
            dl[1] = f2tf(v.y - __uint_as_float(h1));
            dl[2] = f2tf(v.z - __uint_as_float(h2));
            dl[3] = f2tf(v.w - __uint_as_float(h3));
        }
        for (int i = tid; i < KT * (DOUT / 4); i += 256) {
            int r = i / (DOUT / 4), c = i % (DOUT / 4);
            float4 v = ((const float4*)W)[(size_t)(kt + r) * (DOUT / 4) + c];
            unsigned* dh = &Wh[r * WS + c * 4];
            unsigned* dl = &Wl[r * WS + c * 4];
            unsigned h0 = f2tf(v.x), h1 = f2tf(v.y), h2 = f2tf(v.z), h3 = f2tf(v.w);
            dh[0] = h0; dh[1] = h1; dh[2] = h2; dh[3] = h3;
            dl[0] = f2tf(v.x - __uint_as_float(h0));
            dl[1] = f2tf(v.y - __uint_as_float(h1));
            dl[2] = f2tf(v.z - __uint_as_float(h2));
            dl[3] = f2tf(v.w - __uint_as_float(h3));
        }
        __syncthreads();
#pragma unroll
        for (int ks = 0; ks < KT; ks += 8) {
            int r0 = nsub * 16 + g;
            unsigned ah0 = Xh[r0 * XS + ks + tig];
            unsigned ah1 = Xh[(r0 + 8) * XS + ks + tig];
            unsigned ah2 = Xh[r0 * XS + ks + tig + 4];
            unsigned ah3 = Xh[(r0 + 8) * XS + ks + tig + 4];
            unsigned al0 = Xl[r0 * XS + ks + tig];
            unsigned al1 = Xl[(r0 + 8) * XS + ks + tig];
            unsigned al2 = Xl[r0 * XS + ks + tig + 4];
            unsigned al3 = Xl[(r0 + 8) * XS + ks + tig + 4];
#pragma unroll
            for (int nb = 0; nb < 8; ++nb) {
                int col = cgp * 64 + nb * 8 + g;
                unsigned bh0 = Wh[(ks + tig) * WS + col];
                unsigned bh1 = Wh[(ks + tig + 4) * WS + col];
                unsigned bl0 = Wl[(ks + tig) * WS + col];
                unsigned bl1 = Wl[(ks + tig + 4) * WS + col];
                asm volatile(
                    "mma.sync.aligned.m16n8k8.row.col.f32.tf32.tf32.f32 "
                    "{%0,%1,%2,%3}, {%4,%5,%6,%7}, {%8,%9}, {%0,%1,%2,%3};"
                    : "+f"(acc[nb][0]), "+f"(acc[nb][1]), "+f"(acc[nb][2]), "+f"(acc[nb][3])
                    : "r"(ah0), "r"(ah1), "r"(ah2), "r"(ah3), "r"(bh0), "r"(bh1));
                asm volatile(
                    "mma.sync.aligned.m16n8k8.row.col.f32.tf32.tf32.f32 "
                    "{%0,%1,%2,%3}, {%4,%5,%6,%7}, {%8,%9}, {%0,%1,%2,%3};"
                    : "+f"(acc[nb][0]), "+f"(acc[nb][1]), "+f"(acc[nb][2]), "+f"(acc[nb][3])
                    : "r"(ah0), "r"(ah1), "r"(ah2), "r"(ah3), "r"(bl0), "r"(bl1));
                asm volatile(
                    "mma.sync.aligned.m16n8k8.row.col.f32.tf32.tf32.f32 "
                    "{%0,%1,%2,%3}, {%4,%5,%6,%7}, {%8,%9}, {%0,%1,%2,%3};"
                    : "+f"(acc[nb][0]), "+f"(acc[nb][1]), "+f"(acc[nb][2]), "+f"(acc[nb][3])
                    : "r"(al0), "r"(al1), "r"(al2), "r"(al3), "r"(bh0), "r"(bh1));
            }
        }
        __syncthreads();
    }
    int node0 = base + nsub * 16 + g;
#pragma unroll
    for (int nb = 0; nb < 8; ++nb) {
        int col = cgp * 64 + nb * 8 + 2 * tig;
        float b0 = 0.f, b1 = 0.f;
        if (BIAS) { b0 = __ldg(bias + col); b1 = __ldg(bias + col + 1); }
        if (node0 < n) {
            float2 v = make_float2(acc[nb][0] + b0, acc[nb][1] + b1);
            *(float2*)(out + (size_t)node0 * DOUT + col) = v;
        }
        if (node0 + 8 < n) {
            float2 v = make_float2(acc[nb][2] + b0, acc[nb][3] + b1);
            *(float2*)(out + (size_t)(node0 + 8) * DOUT + col) = v;
        }
    }
    if (STATS) {
        __syncthreads();
        int rows = n - base; if (rows > NT) rows = NT;
        constexpr int LPC = 256 / DOUT;
        int col = tid % DOUT, sub = tid / DOUT;
        float s = 0.f, q = 0.f;
        for (int r = sub; r < rows; r += LPC) {
            float v = out[(size_t)(base + r) * DOUT + col];
            s += v; q += v * v;
        }
        __shared__ float red[512];
        red[tid] = s; red[256 + tid] = q;
        __syncthreads();
        if (sub == 0) {
            for (int k = 1; k < LPC; ++k) { s += red[k * DOUT + col]; q += red[256 + k * DOUT + col]; }
            atomicAdd(mean + col, s);
            atomicAdd(sq + col, q);
        }
        __threadfence();
        __shared__ int s_tick;
        if (tid == 0) s_tick = atomicAdd(ticket, 1);
        __syncthreads();
        if (s_tick == gridDim.x - 1) {
            __threadfence();
            if (tid < DOUT) {
                float inv = 1.0f / (float)n;
                float mu = ((volatile float*)mean)[tid] * inv;
                float var = ((volatile float*)sq)[tid] * inv - mu * mu;
                float scv = __ldg(bng + tid) * rsqrtf(var + 1e-5f);
                scale[tid] = scv;
                shift[tid] = __ldg(bnb + tid) - mu * scv;
                mean[tid] = 0.f;
                sq[tid] = 0.f;
            }
            if (tid == 0) *ticket = 0;
        }
    }
    if (SCORES) {
        __syncthreads();
        constexpr int TPN2 = 256 / NT;
        constexpr int HPT = HEADSN / TPN2;
        constexpr int C = DOUT / HEADSN;
        int nodeL = tid / TPN2, part = tid % TPN2;
        int node = base + nodeL;
        if (node < n) {
            const float* row = out + (size_t)node * DOUT;
#pragma unroll
            for (int hh = 0; hh < HPT; ++hh) {
                int head = part * HPT + hh;
                float ps = 0.f, pd = 0.f;
#pragma unroll
                for (int c4 = 0; c4 < C / 4; ++c4) {
                    float4 v = *(const float4*)(row + head * C + c4 * 4);
                    float4 a = __ldg((const float4*)asrc + head * (C / 4) + c4);
                    float4 d = __ldg((const float4*)adst + head * (C / 4) + c4);
                    ps += v.x * a.x + v.y * a.y + v.z * a.z + v.w * a.w;
                    pd += v.x * d.x + v.y * d.y + v.z * d.z + v.w * d.w;
                }
                ssO[(size_t)node * HEADSN + head] = ps;
                sdO[(size_t)node * HEADSN + head] = pd;
            }
        }
    }
}

// ---------------- L3: BN stats + raw mean-pool in ONE pass; ticket-final writes out ----
__global__ void k_bn_pool(const float* __restrict__ src, const int* __restrict__ batch,
                          float* mean, float* sq,
                          const float* __restrict__ bng, const float* __restrict__ bnb,
                          float* psum, float* cnt, int* ticket,
                          float* __restrict__ outF, int G, int n) {
    constexpr int DOUT = 64;
    constexpr int LPC = 4;   // 256/64
    constexpr int NPB = 64;
    int tid = threadIdx.x;
    int col = tid % DOUT, sub = tid / DOUT;
    int base = blockIdx.x * NPB;
    int end = base + NPB; if (end > n) end = n;
    float s = 0.f, q = 0.f;
    float ps = 0.f; int curg = -1; float pc = 0.f;
    for (int nn = base + sub; nn < end; nn += LPC) {
        float v = src[(size_t)nn * DOUT + col];
        s += v; q += v * v;
        int gg = __ldg(batch + nn);
        if (gg != curg) {
            if (curg >= 0) {
                atomicAdd(&psum[(size_t)curg * DOUT + col], ps);
                if (col == 0) atomicAdd(&cnt[curg], pc);
            }
            ps = 0.f; pc = 0.f; curg = gg;
        }
        ps += v; pc += 1.f;
    }
    if (curg >= 0) {
        atomicAdd(&psum[(size_t)curg * DOUT + col], ps);
        if (col == 0) atomicAdd(&cnt[curg], pc);
    }
    __shared__ float sh[512];
    sh[tid] = s; sh[256 + tid] = q;
    __syncthreads();
    if (sub == 0) {
        for (int k = 1; k < LPC; ++k) { s += sh[k * DOUT + col]; q += sh[256 + k * DOUT + col]; }
        atomicAdd(mean + col, s);
        atomicAdd(sq + col, q);
    }
    __threadfence();
    __shared__ int s_tick;
    if (tid == 0) s_tick = atomicAdd(ticket, 1);
    __syncthreads();
    if (s_tick == gridDim.x - 1) {
        __threadfence();
        __shared__ float ssc[DOUT], ssh[DOUT];
        if (tid < DOUT) {
            float inv = 1.0f / (float)n;
            float mu = ((volatile float*)mean)[tid] * inv;
            float var = ((volatile float*)sq)[tid] * inv - mu * mu;
            float scv = __ldg(bng + tid) * rsqrtf(var + 1e-5f);
            ssc[tid] = scv;
            ssh[tid] = __ldg(bnb + tid) - mu * scv;
            mean[tid] = 0.f;
            sq[tid] = 0.f;
        }
        __syncthreads();
        for (int i = tid; i < G * DOUT; i += 256) {
            int gg = i / DOUT, c = i % DOUT;
            float cn = fmaxf(((volatile float*)cnt)[gg], 1.0f);
            float raw = ((volatile float*)psum)[i];
            outF[i] = ssc[c] * (raw / cn) + ssh[c];
            psum[i] = 0.f;
        }
        for (int i = tid; i < G; i += 256) cnt[i] = 0.f;
        if (tid == 0) *ticket = 0;
    }
}

// ---------------- L0 gather @ d=16: edge-parallel, warp per node ----------------
__global__ void __launch_bounds__(256)
k_gather16(const int* __restrict__ rowptr, const int2* __restrict__ pack,
           const float* __restrict__ dis, const float* __restrict__ x,
           float* __restrict__ out, int n) {
    int warp = (blockIdx.x * 256 + threadIdx.x) >> 5;
    int lane = threadIdx.x & 31;
    if (warp >= n) return;
    int eg = lane >> 2, sub = lane & 3;
    float dc = __ldg(dis + warp);
    float4 acc = make_float4(0.f, 0.f, 0.f, 0.f);
    int s0 = __ldg(rowptr + warp), s1 = __ldg(rowptr + warp + 1);
    for (int j = s0 + eg; j < s1; j += 8) {
        int2 p = __ldg(pack + j);
        float w = __int_as_float(p.y) * dc;
        float4 v = __ldg((const float4*)x + (size_t)p.x * 4 + sub);
        acc.x += v.x * w; acc.y += v.y * w; acc.z += v.z * w; acc.w += v.w * w;
    }
#pragma unroll
    for (int off = 4; off <= 16; off <<= 1) {
        acc.x += __shfl_xor_sync(0xffffffff, acc.x, off);
        acc.y += __shfl_xor_sync(0xffffffff, acc.y, off);
        acc.z += __shfl_xor_sync(0xffffffff, acc.z, off);
        acc.w += __shfl_xor_sync(0xffffffff, acc.w, off);
    }
    if (eg == 0) {
        float4 v = __ldg((const float4*)x + (size_t)warp * 4 + sub);
        float w = dc * dc;
        acc.x += v.x * w; acc.y += v.y * w; acc.z += v.z * w; acc.w += v.w * w;
        ((float4*)out)[(size_t)warp * 4 + sub] = acc;
    }
}

// ---------------- generic GCN gather (proven R6 shape) ----------------
template <int TPN, bool BIASP, bool AFFINE, bool RELUIN>
__global__ void __launch_bounds__(256)
k_gather(const int* __restrict__ rowptr, const int2* __restrict__ pack,
         const float* __restrict__ dis, const float* __restrict__ h,
         const float* __restrict__ bias,
         const float* __restrict__ sc_, const float* __restrict__ sh_,
         float* __restrict__ out, int n) {
    int t = blockIdx.x * 256 + threadIdx.x;
    int node = t / TPN, sub = t % TPN;
    if (node >= n) return;
    float4 sc, sh;
    if (AFFINE) { sc = __ldg((const float4*)sc_ + sub); sh = __ldg((const float4*)sh_ + sub); }
    float dc = __ldg(dis + node);
    float4 acc = make_float4(0.f, 0.f, 0.f, 0.f);
    if (BIASP) acc = __ldg((const float4*)bias + sub);
    {
        float4 v = __ldg((const float4*)h + (size_t)node * TPN + sub);
        if (AFFINE) {
            v.x = v.x * sc.x + sh.x; v.y = v.y * sc.y + sh.y;
            v.z = v.z * sc.z + sh.z; v.w = v.w * sc.w + sh.w;
        }
        if (RELUIN) { v.x = lrelu(v.x); v.y = lrelu(v.y); v.z = lrelu(v.z); v.w = lrelu(v.w); }
        float w = dc * dc;
        acc.x += v.x * w; acc.y += v.y * w; acc.z += v.z * w; acc.w += v.w * w;
    }
    int s0 = __ldg(rowptr + node), s1 = __ldg(rowptr + node + 1);
#pragma unroll 4
    for (int j = s0; j < s1; ++j) {
        int2 p = __ldg(pack + j);
        float w = __int_as_float(p.y) * dc;
        float4 v = __ldg((const float4*)h + (size_t)p.x * TPN + sub);
        if (AFFINE) {
            v.x = v.x * sc.x + sh.x; v.y = v.y * sc.y + sh.y;
            v.z = v.z * sc.z + sh.z; v.w = v.w * sc.w + sh.w;
        }
        if (RELUIN) { v.x = lrelu(v.x); v.y = lrelu(v.y); v.z = lrelu(v.z); v.w = lrelu(v.w); }
        acc.x += v.x * w; acc.y += v.y * w; acc.z += v.z * w; acc.w += v.w * w;
    }
    ((float4*)out)[(size_t)node * TPN + sub] = acc;
}

// ---------------- GAT: fused BRANCHLESS online softmax + weighted gather + residual ----
template <int TPN, int H, bool RELU>
__global__ void __launch_bounds__(256)
k_gat_fused(const int* __restrict__ rowptr, const int2* __restrict__ pack,
            const float* __restrict__ ss, const float* __restrict__ sd,
            const float* __restrict__ h2, const float* __restrict__ bias,
            const float* __restrict__ resraw,
            const float* __restrict__ sc_, const float* __restrict__ sh_,
            float* __restrict__ out, int n) {
    constexpr int C = TPN * 4 / H;
    int t = blockIdx.x * 256 + threadIdx.x;
    int node = t / TPN, sub = t % TPN;
    if (node >= n) return;
    int head = (sub * 4) / C;
    float sdv = __ldg(sd + (size_t)node * H + head);

    float m = lrelu(__ldg(ss + (size_t)node * H + head) + sdv);
    float wsum = 1.0f;
    float4 acc = __ldg((const float4*)h2 + (size_t)node * TPN + sub);

    int s0 = __ldg(rowptr + node), s1 = __ldg(rowptr + node + 1);
#pragma unroll 4
    for (int j = s0; j < s1; ++j) {
        int r = __ldg(pack + j).x;
        float e = lrelu(__ldg(ss + (size_t)r * H + head) + sdv);
        float4 v = __ldg((const float4*)h2 + (size_t)r * TPN + sub);
        // branchless online update: alpha = 1 when m stays max
        float nm = fmaxf(m, e);
        float alpha = __expf(m - nm);
        float w = __expf(e - nm);
        wsum = wsum * alpha + w;
        acc.x = acc.x * alpha + v.x * w;
        acc.y = acc.y * alpha + v.y * w;
        acc.z = acc.z * alpha + v.z * w;
        acc.w = acc.w * alpha + v.w * w;
        m = nm;
    }
    float inv = 1.0f / wsum;
    float4 bv = __ldg((const float4*)bias + sub);
    float4 xr = __ldg((const float4*)resraw + (size_t)node * TPN + sub);
    float4 sc = __ldg((const float4*)sc_ + sub);
    float4 sh = __ldg((const float4*)sh_ + sub);
    float4 o;
    o.x = acc.x * inv + bv.x + (xr.x * sc.x + sh.x);
    o.y = acc.y * inv + bv.y + (xr.y * sc.y + sh.y);
    o.z = acc.z * inv + bv.z + (xr.z * sc.z + sh.z);
    o.w = acc.w * inv + bv.w + (xr.w * sc.w + sh.w);
    if (RELU) { o.x = lrelu(o.x); o.y = lrelu(o.y); o.z = lrelu(o.z); o.w = lrelu(o.w); }
    ((float4*)out)[(size_t)node * TPN + sub] = o;
}

// ---------------- host ----------------
static inline int GRID(long long t) { return (int)((t + 255) / 256); }

extern "C" void kernel_launch(void* const* d_in, const int* in_sizes, int n_in,
                              void* d_out, int out_size) {
    const float* x     = (const float*)d_in[0];
    const int*   ei    = (const int*)d_in[1];
    const int*   batch = (const int*)d_in[2];
    const int n = in_sizes[0] / 16;
    const int E = in_sizes[1] / 2;
    const int* rowp = ei;
    const int* colp = ei + E;

    const float* gcn_w[4] = {(const float*)d_in[3], (const float*)d_in[7],
                             (const float*)d_in[11], (const float*)d_in[15]};
    const float* gcn_b[4] = {(const float*)d_in[4], (const float*)d_in[8],
                             (const float*)d_in[12], (const float*)d_in[16]};
    const float* bn_g[4]  = {(const float*)d_in[5], (const float*)d_in[9],
                             (const float*)d_in[13], (const float*)d_in[17]};
    const float* bn_b[4]  = {(const float*)d_in[6], (const float*)d_in[10],
                             (const float*)d_in[14], (const float*)d_in[18]};
    const float* gat_w0    = (const float*)d_in[19];
    const float* gat_asrc0 = (const float*)d_in[20];
    const float* gat_adst0 = (const float*)d_in[21];
    const float* gat_b0    = (const float*)d_in[22];
    const float* gat_w2    = (const float*)d_in[23];
    const float* gat_asrc2 = (const float*)d_in[24];
    const float* gat_adst2 = (const float*)d_in[25];
    const float* gat_b2    = (const float*)d_in[26];

    float *A, *B, *C, *dis, *ss, *sd, *mean, *sq, *scale, *shift, *psum, *cnt;
    int *deg, *rowptr, *cursor, *tick;
    int2* pack;
    cudaGetSymbolAddress((void**)&A, g_A);
    cudaGetSymbolAddress((void**)&B, g_B);
    cudaGetSymbolAddress((void**)&C, g_C);
    cudaGetSymbolAddress((void**)&dis, g_dis);
    cudaGetSymbolAddress((void**)&deg, g_deg);
    cudaGetSymbolAddress((void**)&rowptr, g_rowptr);
    cudaGetSymbolAddress((void**)&cursor, g_cursor);
    cudaGetSymbolAddress((void**)&pack, g_pack);
    cudaGetSymbolAddress((void**)&ss, g_ss);
    cudaGetSymbolAddress((void**)&sd, g_sd);
    cudaGetSymbolAddress((void**)&mean, g_mean);
    cudaGetSymbolAddress((void**)&sq, g_sq);
    cudaGetSymbolAddress((void**)&scale, g_scale);
    cudaGetSymbolAddress((void**)&shift, g_shift);
    cudaGetSymbolAddress((void**)&psum, g_psum);
    cudaGetSymbolAddress((void**)&cnt, g_cnt);
    cudaGetSymbolAddress((void**)&tick, g_tick);
    float* out = (float*)d_out;
    const int G = out_size / 64;

    // ---- CSR build: 3 launches (single-pass scan; deg reset in csr_fill) ----
    const int nb = (n + SCAN_CHUNK - 1) / SCAN_CHUNK;
    k_deg_count<<<GRID((E + 3) / 4), 256>>>(colp, deg, E);
    k_scan_dis<<<nb, SCAN_CHUNK>>>(deg, rowptr, cursor, dis, n);
    k_csr_fill<<<GRID(E), 256>>>(rowp, colp, dis, cursor, pack, deg, E, n);

    // ----- layer 0 -----
    k_gather16<<<(n + 7) / 8, 256>>>(rowptr, pack, dis, x, C, n);
    k_gemm<16, 64, true, false, true, false><<<(n + 127) / 128, 256>>>(
        C, gcn_w[0], gcn_b[0], nullptr, nullptr, B,
        mean, sq, scale, shift, bn_g[0], bn_b[0], tick + 0,
        nullptr, nullptr, nullptr, nullptr, n);
    k_gemm<64, 64, false, true, false, true><<<(n + 127) / 128, 256>>>(
        B, gat_w0, nullptr, scale, shift, A,
        nullptr, nullptr, nullptr, nullptr, nullptr, nullptr, nullptr,
        gat_asrc0, gat_adst0, ss, sd, n);
    k_gat_fused<16, 4, true><<<(n + 15) / 16, 256>>>(
        rowptr, pack, ss, sd, A, gat_b0, B, scale, shift, B, n);

    // ----- layer 1 -----
    k_gather<16, false, false, false><<<(n + 15) / 16, 256>>>(
        rowptr, pack, dis, B, nullptr, nullptr, nullptr, C, n);
    k_gemm<64, 128, true, false, true, false><<<(n + 63) / 64, 256>>>(
        C, gcn_w[1], gcn_b[1], nullptr, nullptr, A,
        mean, sq, scale, shift, bn_g[1], bn_b[1], tick + 1,
        nullptr, nullptr, nullptr, nullptr, n);

    // ----- layer 2 (L1 bn+relu folded into gather input) -----
    k_gather<32, false, true, true><<<(n + 7) / 8, 256>>>(
        rowptr, pack, dis, A, nullptr, scale, shift, C, n);
    k_gemm<128, 128, true, false, true, false><<<(n + 63) / 64, 256>>>(
        C, gcn_w[2], gcn_b[2], nullptr, nullptr, B,
        mean, sq, scale, shift, bn_g[2], bn_b[2], tick + 2,
        nullptr, nullptr, nullptr, nullptr, n);
    k_gemm<128, 128, false, true, false, true><<<(n + 63) / 64, 256>>>(
        B, gat_w2, nullptr, scale, shift, A,
        nullptr, nullptr, nullptr, nullptr, nullptr, nullptr, nullptr,
        gat_asrc2, gat_adst2, ss, sd, n);
    k_gat_fused<32, 4, true><<<(n + 7) / 8, 256>>>(
        rowptr, pack, ss, sd, A, gat_b2, B, scale, shift, B, n);

    // ----- layer 3: gemm, gather(+bias), fused BN-stats + mean-pool -----
    k_gemm<128, 64, false, false, false, false><<<(n + 127) / 128, 256>>>(
        B, gcn_w[3], nullptr, nullptr, nullptr, A,
        nullptr, nullptr, nullptr, nullptr, nullptr, nullptr, nullptr,
        nullptr, nullptr, nullptr, nullptr, n);
    k_gather<16, true, false, false><<<(n + 15) / 16, 256>>>(
        rowptr, pack, dis, A, gcn_b[3], nullptr, nullptr, C, n);
    k_bn_pool<<<(n + 63) / 64, 256>>>(
        C, batch, mean, sq, bn_g[3], bn_b[3], psum, cnt, tick + 3, out, G, n);
}

// round 16
// speedup vs baseline: 1.1023x; 1.0124x over previous
#include <cuda_runtime.h>
#include <cuda_bf16.h>
#include <math.h>

#define NMAX 100000
#define EMAX 1600000
#define GMAX 256
#define HEADSN 4
#define SCAN_CHUNK 512

// ---------------- scratch ----------------
__device__ __align__(16) float g_A[(size_t)NMAX * 128];
__device__ __align__(16) float g_B[(size_t)NMAX * 128];
__device__ __align__(16) float g_C[(size_t)NMAX * 128];
__device__ __align__(16) float g_dis[NMAX];
__device__ __align__(16) int   g_deg[NMAX];               // zero-init; csr_fill self-resets
__device__ __align__(16) int   g_rowptr[NMAX + 1];
__device__ __align__(16) int   g_cursor[NMAX];
__device__ __align__(16) int2  g_pack[EMAX];              // (src, bits(dis[src]))
__device__ __align__(16) float g_ss[NMAX * HEADSN];
__device__ __align__(16) float g_sd[NMAX * HEADSN];
__device__ __align__(16) float g_mean[128];               // zero-init; final blocks reset
__device__ __align__(16) float g_sq[128];
__device__ __align__(16) float g_scale[128];
__device__ __align__(16) float g_shift[128];
__device__ __align__(16) float g_psum[GMAX * 64];         // raw pool sums; self-reset
__device__ __align__(16) float g_cnt[GMAX];               // self-reset
__device__            int   g_tick[8];                    // zero-init tickets; self-reset

__device__ __forceinline__ float lrelu(float v) { return v > 0.f ? v : 0.2f * v; }
__device__ __forceinline__ unsigned f2tf(float f) {
    unsigned u; asm("cvt.rna.tf32.f32 %0, %1;" : "=r"(u) : "f"(f)); return u;
}

// ---------------- CSR build ----------------
__global__ void k_deg_count(const int* __restrict__ colp, int* deg, int E) {
    int i0 = (blockIdx.x * blockDim.x + threadIdx.x) * 4;
#pragma unroll
    for (int k = 0; k < 4; ++k) {
        int i = i0 + k;
        if (i < E) atomicAdd(&deg[__ldg(colp + i)], 1);
    }
}
// single-pass scan: each block sums deg[0..chunk_start) directly, then scans its chunk.
__global__ void k_scan_dis(const int* __restrict__ deg,
                           int* rowptr, int* cursor, float* dis, int n) {
    __shared__ int sh[SCAN_CHUNK];
    int tid = threadIdx.x, bid = blockIdx.x;
    int limit = bid * SCAN_CHUNK;
    int part = 0;
    for (int j = tid; j < limit; j += SCAN_CHUNK) part += __ldg(deg + j);
    sh[tid] = part;
    __syncthreads();
    for (int off = SCAN_CHUNK / 2; off > 0; off >>= 1) {
        if (tid < off) sh[tid] += sh[tid + off];
        __syncthreads();
    }
    int base = sh[0];
    __syncthreads();
    int i = limit + tid;
    int v = (i < n) ? __ldg(deg + i) : 0;
    sh[tid] = v;
    __syncthreads();
    for (int off = 1; off < SCAN_CHUNK; off <<= 1) {
        int t = (tid >= off) ? sh[tid - off] : 0;
        __syncthreads();
        sh[tid] += t;
        __syncthreads();
    }
    if (i < n) {
        int excl = base + sh[tid] - v;
        rowptr[i] = excl;
        cursor[i] = excl;
        dis[i] = rsqrtf(1.0f + (float)v);
        if (i == n - 1) rowptr[n] = excl + v;
    }
}
// fill packed CSR; also resets deg for next replay (doesn't read deg)
__global__ void k_csr_fill(const int* __restrict__ rowp, const int* __restrict__ colp,
                           const float* __restrict__ dis, int* cursor, int2* pack,
                           int* deg, int E, int n) {
    int e = blockIdx.x * blockDim.x + threadIdx.x;
    if (e < n) deg[e] = 0;
    if (e >= E) return;
    int c = colp[e];
    int r = rowp[e];
    int pos = atomicAdd(&cursor[c], 1);
    pack[pos] = make_int2(r, __float_as_int(__ldg(dis + r)));
}

// ---------------- split-TF32 GEMM (+ fused BN stats / GAT scores epilogues) ------------
template <int DIN, int DOUT, bool BIAS, bool AFFINE, bool STATS, bool SCORES>
__global__ void k_gemm(const float* __restrict__ X, const float* __restrict__ W,
                       const float* __restrict__ bias,
                       const float* __restrict__ sc_, const float* __restrict__ sh_,
                       float* __restrict__ out,
                       float* mean, float* sq, float* scale, float* shift,
                       const float* __restrict__ bng, const float* __restrict__ bnb,
                       int* ticket,
                       const float* __restrict__ asrc, const float* __restrict__ adst,
                       float* __restrict__ ssO, float* __restrict__ sdO, int n) {
    constexpr int NT = (DOUT >= 128) ? 64 : 128;
    constexpr int KT = (DIN < 32) ? DIN : 32;
    constexpr int NW = NT / 16;
    constexpr int XS = KT + 4;
    constexpr int WS = DOUT + 4;
    __shared__ unsigned Xh[NT * XS];
    __shared__ unsigned Xl[NT * XS];
    __shared__ unsigned Wh[KT * WS];
    __shared__ unsigned Wl[KT * WS];

    const int tid = threadIdx.x;
    const int wid = tid >> 5, lane = tid & 31;
    const int g = lane >> 2, tig = lane & 3;
    const int nsub = wid % NW, cgp = wid / NW;
    const int base = blockIdx.x * NT;

    float acc[8][4];
#pragma unroll
    for (int i = 0; i < 8; ++i)
#pragma unroll
        for (int j = 0; j < 4; ++j) acc[i][j] = 0.f;

    for (int kt = 0; kt < DIN; kt += KT) {
        for (int i = tid; i < NT * (KT / 4); i += 256) {
            int r = i / (KT / 4), c = i % (KT / 4);
            int node = base + r;
            float4 v = make_float4(0.f, 0.f, 0.f, 0.f);
            if (node < n) v = ((const float4*)X)[(size_t)node * (DIN / 4) + kt / 4 + c];
            if (AFFINE) {
                float4 sc = __ldg((const float4*)sc_ + kt / 4 + c);
                float4 sh = __ldg((const float4*)sh_ + kt / 4 + c);
                v.x = v.x * sc.x + sh.x; v.y = v.y * sc.y + sh.y;
                v.z = v.z * sc.z + sh.z; v.w = v.w * sc.w + sh.w;
            }
            unsigned* dh = &Xh[r * XS + c * 4];
            unsigned* dl = &Xl[r * XS + c * 4];
            unsigned h0 = f2tf(v.x), h1 = f2tf(v.y), h2 = f2tf(v.z), h3 = f2tf(v.w);
            dh[0] = h0; dh[1] = h1; dh[2] = h2; dh[3] = h3;
            dl[0] = f2tf(v.x - __uint_as_float(h0));
            dl[1] = f2tf(v.y - __uint_as_float(h1));
            dl[2] = f2tf(v.z - __uint_as_float(h2));
            dl[3] = f2tf(v.w - __uint_as_float(h3));
        }
        for (int i = tid; i < KT * (DOUT / 4); i += 256) {
            int r = i / (DOUT / 4), c = i % (DOUT / 4);
            float4 v = ((const float4*)W)[(size_t)(kt + r) * (DOUT / 4) + c];
            unsigned* dh = &Wh[r * WS + c * 4];
            unsigned* dl = &Wl[r * WS + c * 4];
            unsigned h0 = f2tf(v.x), h1 = f2tf(v.y), h2 = f2tf(v.z), h3 = f2tf(v.w);
            dh[0] = h0; dh[1] = h1; dh[2] = h2; dh[3] = h3;
            dl[0] = f2tf(v.x - __uint_as_float(h0));
            dl[1] = f2tf(v.y - __uint_as_float(h1));
            dl[2] = f2tf(v.z - __uint_as_float(h2));
            dl[3] = f2tf(v.w - __uint_as_float(h3));
        }
        __syncthreads();
#pragma unroll
        for (int ks = 0; ks < KT; ks += 8) {
            int r0 = nsub * 16 + g;
            unsigned ah0 = Xh[r0 * XS + ks + tig];
            unsigned ah1 = Xh[(r0 + 8) * XS + ks + tig];
            unsigned ah2 = Xh[r0 * XS + ks + tig + 4];
            unsigned ah3 = Xh[(r0 + 8) * XS + ks + tig + 4];
            unsigned al0 = Xl[r0 * XS + ks + tig];
            unsigned al1 = Xl[(r0 + 8) * XS + ks + tig];
            unsigned al2 = Xl[r0 * XS + ks + tig + 4];
            unsigned al3 = Xl[(r0 + 8) * XS + ks + tig + 4];
#pragma unroll
            for (int nb = 0; nb < 8; ++nb) {
                int col = cgp * 64 + nb * 8 + g;
                unsigned bh0 = Wh[(ks + tig) * WS + col];
                unsigned bh1 = Wh[(ks + tig + 4) * WS + col];
                unsigned bl0 = Wl[(ks + tig) * WS + col];
                unsigned bl1 = Wl[(ks + tig + 4) * WS + col];
                asm volatile(
                    "mma.sync.aligned.m16n8k8.row.col.f32.tf32.tf32.f32 "
                    "{%0,%1,%2,%3}, {%4,%5,%6,%7}, {%8,%9}, {%0,%1,%2,%3};"
                    : "+f"(acc[nb][0]), "+f"(acc[nb][1]), "+f"(acc[nb][2]), "+f"(acc[nb][3])
                    : "r"(ah0), "r"(ah1), "r"(ah2), "r"(ah3), "r"(bh0), "r"(bh1));
                asm volatile(
                    "mma.sync.aligned.m16n8k8.row.col.f32.tf32.tf32.f32 "
                    "{%0,%1,%2,%3}, {%4,%5,%6,%7}, {%8,%9}, {%0,%1,%2,%3};"
                    : "+f"(acc[nb][0]), "+f"(acc[nb][1]), "+f"(acc[nb][2]), "+f"(acc[nb][3])
                    : "r"(ah0), "r"(ah1), "r"(ah2), "r"(ah3), "r"(bl0), "r"(bl1));
                asm volatile(
                    "mma.sync.aligned.m16n8k8.row.col.f32.tf32.tf32.f32 "
                    "{%0,%1,%2,%3}, {%4,%5,%6,%7}, {%8,%9}, {%0,%1,%2,%3};"
                    : "+f"(acc[nb][0]), "+f"(acc[nb][1]), "+f"(acc[nb][2]), "+f"(acc[nb][3])
                    : "r"(al0), "r"(al1), "r"(al2), "r"(al3), "r"(bh0), "r"(bh1));
            }
        }
        __syncthreads();
    }
    int node0 = base + nsub * 16 + g;
#pragma unroll
    for (int nb = 0; nb < 8; ++nb) {
        int col = cgp * 64 + nb * 8 + 2 * tig;
        float b0 = 0.f, b1 = 0.f;
        if (BIAS) { b0 = __ldg(bias + col); b1 = __ldg(bias + col + 1); }
        if (node0 < n) {
            float2 v = make_float2(acc[nb][0] + b0, acc[nb][1] + b1);
            *(float2*)(out + (size_t)node0 * DOUT + col) = v;
        }
        if (node0 + 8 < n) {
            float2 v = make_float2(acc[nb][2] + b0, acc[nb][3] + b1);
            *(float2*)(out + (size_t)(node0 + 8) * DOUT + col) = v;
        }
    }
    if (STATS) {
        __syncthreads();
        int rows = n - base; if (rows > NT) rows = NT;
        constexpr int LPC = 256 / DOUT;
        int col = tid % DOUT, sub = tid / DOUT;
        float s = 0.f, q = 0.f;
        for (int r = sub; r < rows; r += LPC) {
            float v = out[(size_t)(base + r) * DOUT + col];
            s += v; q += v * v;
        }
        __shared__ float red[512];
        red[tid] = s; red[256 + tid] = q;
        __syncthreads();
        if (sub == 0) {
            for (int k = 1; k < LPC; ++k) { s += red[k * DOUT + col]; q += red[256 + k * DOUT + col]; }
            atomicAdd(mean + col, s);
            atomicAdd(sq + col, q);
        }
        __threadfence();
        __shared__ int s_tick;
        if (tid == 0) s_tick = atomicAdd(ticket, 1);
        __syncthreads();
        if (s_tick == gridDim.x - 1) {
            __threadfence();
            if (tid < DOUT) {
                float inv = 1.0f / (float)n;
                float mu = ((volatile float*)mean)[tid] * inv;
                float var = ((volatile float*)sq)[tid] * inv - mu * mu;
                float scv = __ldg(bng + tid) * rsqrtf(var + 1e-5f);
                scale[tid] = scv;
                shift[tid] = __ldg(bnb + tid) - mu * scv;
                mean[tid] = 0.f;
                sq[tid] = 0.f;
            }
            if (tid == 0) *ticket = 0;
        }
    }
    if (SCORES) {
        __syncthreads();
        constexpr int TPN2 = 256 / NT;
        constexpr int HPT = HEADSN / TPN2;
        constexpr int C = DOUT / HEADSN;
        int nodeL = tid / TPN2, part = tid % TPN2;
        int node = base + nodeL;
        if (node < n) {
            const float* row = out + (size_t)node * DOUT;
#pragma unroll
            for (int hh = 0; hh < HPT; ++hh) {
                int head = part * HPT + hh;
                float ps = 0.f, pd = 0.f;
#pragma unroll
                for (int c4 = 0; c4 < C / 4; ++c4) {
                    float4 v = *(const float4*)(row + head * C + c4 * 4);
                    float4 a = __ldg((const float4*)asrc + head * (C / 4) + c4);
                    float4 d = __ldg((const float4*)adst + head * (C / 4) + c4);
                    ps += v.x * a.x + v.y * a.y + v.z * a.z + v.w * a.w;
                    pd += v.x * d.x + v.y * d.y + v.z * d.z + v.w * d.w;
                }
                ssO[(size_t)node * HEADSN + head] = ps;
                sdO[(size_t)node * HEADSN + head] = pd;
            }
        }
    }
}

// ---------------- L3: BN stats + raw mean-pool in ONE pass; ticket-final writes out ----
__global__ void k_bn_pool(const float* __restrict__ src, const int* __restrict__ batch,
                          float* mean, float* sq,
                          const float* __restrict__ bng, const float* __restrict__ bnb,
                          float* psum, float* cnt, int* ticket,
                          float* __restrict__ outF, int G, int n) {
    constexpr int DOUT = 64;
    constexpr int LPC = 4;   // 256/64
    constexpr int NPB = 64;
    int tid = threadIdx.x;
    int col = tid % DOUT, sub = tid / DOUT;
    int base = blockIdx.x * NPB;
    int end = base + NPB; if (end > n) end = n;
    float s = 0.f, q = 0.f;
    float ps = 0.f; int curg = -1; float pc = 0.f;
    for (int nn = base + sub; nn < end; nn += LPC) {
        float v = src[(size_t)nn * DOUT + col];
        s += v; q += v * v;
        int gg = __ldg(batch + nn);
        if (gg != curg) {
            if (curg >= 0) {
                atomicAdd(&psum[(size_t)curg * DOUT + col], ps);
                if (col == 0) atomicAdd(&cnt[curg], pc);
            }
            ps = 0.f; pc = 0.f; curg = gg;
        }
        ps += v; pc += 1.f;
    }
    if (curg >= 0) {
        atomicAdd(&psum[(size_t)curg * DOUT + col], ps);
        if (col == 0) atomicAdd(&cnt[curg], pc);
    }
    __shared__ float sh[512];
    sh[tid] = s; sh[256 + tid] = q;
    __syncthreads();
    if (sub == 0) {
        for (int k = 1; k < LPC; ++k) { s += sh[k * DOUT + col]; q += sh[256 + k * DOUT + col]; }
        atomicAdd(mean + col, s);
        atomicAdd(sq + col, q);
    }
    __threadfence();
    __shared__ int s_tick;
    if (tid == 0) s_tick = atomicAdd(ticket, 1);
    __syncthreads();
    if (s_tick == gridDim.x - 1) {
        __threadfence();
        __shared__ float ssc[DOUT], ssh[DOUT];
        if (tid < DOUT) {
            float inv = 1.0f / (float)n;
            float mu = ((volatile float*)mean)[tid] * inv;
            float var = ((volatile float*)sq)[tid] * inv - mu * mu;
            float scv = __ldg(bng + tid) * rsqrtf(var + 1e-5f);
            ssc[tid] = scv;
            ssh[tid] = __ldg(bnb + tid) - mu * scv;
            mean[tid] = 0.f;
            sq[tid] = 0.f;
        }
        __syncthreads();
        for (int i = tid; i < G * DOUT; i += 256) {
            int gg = i / DOUT, c = i % DOUT;
            float cn = fmaxf(((volatile float*)cnt)[gg], 1.0f);
            float raw = ((volatile float*)psum)[i];
            outF[i] = ssc[c] * (raw / cn) + ssh[c];
            psum[i] = 0.f;
        }
        for (int i = tid; i < G; i += 256) cnt[i] = 0.f;
        if (tid == 0) *ticket = 0;
    }
}

// ---------------- L0 gather @ d=16: edge-parallel, warp per node ----------------
__global__ void __launch_bounds__(256)
k_gather16(const int* __restrict__ rowptr, const int2* __restrict__ pack,
           const float* __restrict__ dis, const float* __restrict__ x,
           float* __restrict__ out, int n) {
    int warp = (blockIdx.x * 256 + threadIdx.x) >> 5;
    int lane = threadIdx.x & 31;
    if (warp >= n) return;
    int eg = lane >> 2, sub = lane & 3;
    float dc = __ldg(dis + warp);
    float4 acc = make_float4(0.f, 0.f, 0.f, 0.f);
    int s0 = __ldg(rowptr + warp), s1 = __ldg(rowptr + warp + 1);
    for (int j = s0 + eg; j < s1; j += 8) {
        int2 p = __ldg(pack + j);
        float w = __int_as_float(p.y) * dc;
        float4 v = __ldg((const float4*)x + (size_t)p.x * 4 + sub);
        acc.x += v.x * w; acc.y += v.y * w; acc.z += v.z * w; acc.w += v.w * w;
    }
#pragma unroll
    for (int off = 4; off <= 16; off <<= 1) {
        acc.x += __shfl_xor_sync(0xffffffff, acc.x, off);
        acc.y += __shfl_xor_sync(0xffffffff, acc.y, off);
        acc.z += __shfl_xor_sync(0xffffffff, acc.z, off);
        acc.w += __shfl_xor_sync(0xffffffff, acc.w, off);
    }
    if (eg == 0) {
        float4 v = __ldg((const float4*)x + (size_t)warp * 4 + sub);
        float w = dc * dc;
        acc.x += v.x * w; acc.y += v.y * w; acc.z += v.z * w; acc.w += v.w * w;
        ((float4*)out)[(size_t)warp * 4 + sub] = acc;
    }
}

// ---------------- generic GCN gather (proven R6 shape) ----------------
template <int TPN, bool BIASP, bool AFFINE, bool RELUIN>
__global__ void __launch_bounds__(256)
k_gather(const int* __restrict__ rowptr, const int2* __restrict__ pack,
         const float* __restrict__ dis, const float* __restrict__ h,
         const float* __restrict__ bias,
         const float* __restrict__ sc_, const float* __restrict__ sh_,
         float* __restrict__ out, int n) {
    int t = blockIdx.x * 256 + threadIdx.x;
    int node = t / TPN, sub = t % TPN;
    if (node >= n) return;
    float4 sc, sh;
    if (AFFINE) { sc = __ldg((const float4*)sc_ + sub); sh = __ldg((const float4*)sh_ + sub); }
    float dc = __ldg(dis + node);
    float4 acc = make_float4(0.f, 0.f, 0.f, 0.f);
    if (BIASP) acc = __ldg((const float4*)bias + sub);
    {
        float4 v = __ldg((const float4*)h + (size_t)node * TPN + sub);
        if (AFFINE) {
            v.x = v.x * sc.x + sh.x; v.y = v.y * sc.y + sh.y;
            v.z = v.z * sc.z + sh.z; v.w = v.w * sc.w + sh.w;
        }
        if (RELUIN) { v.x = lrelu(v.x); v.y = lrelu(v.y); v.z = lrelu(v.z); v.w = lrelu(v.w); }
        float w = dc * dc;
        acc.x += v.x * w; acc.y += v.y * w; acc.z += v.z * w; acc.w += v.w * w;
    }
    int s0 = __ldg(rowptr + node), s1 = __ldg(rowptr + node + 1);
#pragma unroll 4
    for (int j = s0; j < s1; ++j) {
        int2 p = __ldg(pack + j);
        float w = __int_as_float(p.y) * dc;
        float4 v = __ldg((const float4*)h + (size_t)p.x * TPN + sub);
        if (AFFINE) {
            v.x = v.x * sc.x + sh.x; v.y = v.y * sc.y + sh.y;
            v.z = v.z * sc.z + sh.z; v.w = v.w * sc.w + sh.w;
        }
        if (RELUIN) { v.x = lrelu(v.x); v.y = lrelu(v.y); v.z = lrelu(v.z); v.w = lrelu(v.w); }
        acc.x += v.x * w; acc.y += v.y * w; acc.z += v.z * w; acc.w += v.w * w;
    }
    ((float4*)out)[(size_t)node * TPN + sub] = acc;
}

// ---------------- GAT: FIXED-REFERENCE softmax + weighted gather + residual -----------
// Softmax is shift-invariant: use the self-score as a fixed reference (no max tracking).
// Scores are bounded (|e-m| << 88) for BN-normalized features, so exp cannot overflow.
template <int TPN, int H, bool RELU>
__global__ void __launch_bounds__(256)
k_gat_fused(const int* __restrict__ rowptr, const int2* __restrict__ pack,
            const float* __restrict__ ss, const float* __restrict__ sd,
            const float* __restrict__ h2, const float* __restrict__ bias,
            const float* __restrict__ resraw,
            const float* __restrict__ sc_, const float* __restrict__ sh_,
            float* __restrict__ out, int n) {
    constexpr int C = TPN * 4 / H;
    int t = blockIdx.x * 256 + threadIdx.x;
    int node = t / TPN, sub = t % TPN;
    if (node >= n) return;
    int head = (sub * 4) / C;
    float sdv = __ldg(sd + (size_t)node * H + head);

    const float m = lrelu(__ldg(ss + (size_t)node * H + head) + sdv);  // fixed reference
    float wsum = 1.0f;                                                  // self: exp(0)=1
    float4 acc = __ldg((const float4*)h2 + (size_t)node * TPN + sub);

    int s0 = __ldg(rowptr + node), s1 = __ldg(rowptr + node + 1);
#pragma unroll 4
    for (int j = s0; j < s1; ++j) {
        int r = __ldg(pack + j).x;
        float e = lrelu(__ldg(ss + (size_t)r * H + head) + sdv);
        float4 v = __ldg((const float4*)h2 + (size_t)r * TPN + sub);
        float w = __expf(e - m);
        wsum += w;
        acc.x += v.x * w; acc.y += v.y * w;
        acc.z += v.z * w; acc.w += v.w * w;
    }
    float inv = 1.0f / wsum;
    float4 bv = __ldg((const float4*)bias + sub);
    float4 xr = __ldg((const float4*)resraw + (size_t)node * TPN + sub);
    float4 sc = __ldg((const float4*)sc_ + sub);
    float4 sh = __ldg((const float4*)sh_ + sub);
    float4 o;
    o.x = acc.x * inv + bv.x + (xr.x * sc.x + sh.x);
    o.y = acc.y * inv + bv.y + (xr.y * sc.y + sh.y);
    o.z = acc.z * inv + bv.z + (xr.z * sc.z + sh.z);
    o.w = acc.w * inv + bv.w + (xr.w * sc.w + sh.w);
    if (RELU) { o.x = lrelu(o.x); o.y = lrelu(o.y); o.z = lrelu(o.z); o.w = lrelu(o.w); }
    ((float4*)out)[(size_t)node * TPN + sub] = o;
}

// ---------------- host ----------------
static inline int GRID(long long t) { return (int)((t + 255) / 256); }

extern "C" void kernel_launch(void* const* d_in, const int* in_sizes, int n_in,
                              void* d_out, int out_size) {
    const float* x     = (const float*)d_in[0];
    const int*   ei    = (const int*)d_in[1];
    const int*   batch = (const int*)d_in[2];
    const int n = in_sizes[0] / 16;
    const int E = in_sizes[1] / 2;
    const int* rowp = ei;
    const int* colp = ei + E;

    const float* gcn_w[4] = {(const float*)d_in[3], (const float*)d_in[7],
                             (const float*)d_in[11], (const float*)d_in[15]};
    const float* gcn_b[4] = {(const float*)d_in[4], (const float*)d_in[8],
                             (const float*)d_in[12], (const float*)d_in[16]};
    const float* bn_g[4]  = {(const float*)d_in[5], (const float*)d_in[9],
                             (const float*)d_in[13], (const float*)d_in[17]};
    const float* bn_b[4]  = {(const float*)d_in[6], (const float*)d_in[10],
                             (const float*)d_in[14], (const float*)d_in[18]};
    const float* gat_w0    = (const float*)d_in[19];
    const float* gat_asrc0 = (const float*)d_in[20];
    const float* gat_adst0 = (const float*)d_in[21];
    const float* gat_b0    = (const float*)d_in[22];
    const float* gat_w2    = (const float*)d_in[23];
    const float* gat_asrc2 = (const float*)d_in[24];
    const float* gat_adst2 = (const float*)d_in[25];
    const float* gat_b2    = (const float*)d_in[26];

    float *A, *B, *C, *dis, *ss, *sd, *mean, *sq, *scale, *shift, *psum, *cnt;
    int *deg, *rowptr, *cursor, *tick;
    int2* pack;
    cudaGetSymbolAddress((void**)&A, g_A);
    cudaGetSymbolAddress((void**)&B, g_B);
    cudaGetSymbolAddress((void**)&C, g_C);
    cudaGetSymbolAddress((void**)&dis, g_dis);
    cudaGetSymbolAddress((void**)&deg, g_deg);
    cudaGetSymbolAddress((void**)&rowptr, g_rowptr);
    cudaGetSymbolAddress((void**)&cursor, g_cursor);
    cudaGetSymbolAddress((void**)&pack, g_pack);
    cudaGetSymbolAddress((void**)&ss, g_ss);
    cudaGetSymbolAddress((void**)&sd, g_sd);
    cudaGetSymbolAddress((void**)&mean, g_mean);
    cudaGetSymbolAddress((void**)&sq, g_sq);
    cudaGetSymbolAddress((void**)&scale, g_scale);
    cudaGetSymbolAddress((void**)&shift, g_shift);
    cudaGetSymbolAddress((void**)&psum, g_psum);
    cudaGetSymbolAddress((void**)&cnt, g_cnt);
    cudaGetSymbolAddress((void**)&tick, g_tick);
    float* out = (float*)d_out;
    const int G = out_size / 64;

    // ---- CSR build: 3 launches ----
    const int nb = (n + SCAN_CHUNK - 1) / SCAN_CHUNK;
    k_deg_count<<<GRID((E + 3) / 4), 256>>>(colp, deg, E);
    k_scan_dis<<<nb, SCAN_CHUNK>>>(deg, rowptr, cursor, dis, n);
    k_csr_fill<<<GRID(E), 256>>>(rowp, colp, dis, cursor, pack, deg, E, n);

    // ----- layer 0 -----
    k_gather16<<<(n + 7) / 8, 256>>>(rowptr, pack, dis, x, C, n);
    k_gemm<16, 64, true, false, true, false><<<(n + 127) / 128, 256>>>(
        C, gcn_w[0], gcn_b[0], nullptr, nullptr, B,
        mean, sq, scale, shift, bn_g[0], bn_b[0], tick + 0,
        nullptr, nullptr, nullptr, nullptr, n);
    k_gemm<64, 64, false, true, false, true><<<(n + 127) / 128, 256>>>(
        B, gat_w0, nullptr, scale, shift, A,
        nullptr, nullptr, nullptr, nullptr, nullptr, nullptr, nullptr,
        gat_asrc0, gat_adst0, ss, sd, n);
    k_gat_fused<16, 4, true><<<(n + 15) / 16, 256>>>(
        rowptr, pack, ss, sd, A, gat_b0, B, scale, shift, B, n);

    // ----- layer 1 -----
    k_gather<16, false, false, false><<<(n + 15) / 16, 256>>>(
        rowptr, pack, dis, B, nullptr, nullptr, nullptr, C, n);
    k_gemm<64, 128, true, false, true, false><<<(n + 63) / 64, 256>>>(
        C, gcn_w[1], gcn_b[1], nullptr, nullptr, A,
        mean, sq, scale, shift, bn_g[1], bn_b[1], tick + 1,
        nullptr, nullptr, nullptr, nullptr, n);

    // ----- layer 2 (L1 bn+relu folded into gather input) -----
    k_gather<32, false, true, true><<<(n + 7) / 8, 256>>>(
        rowptr, pack, dis, A, nullptr, scale, shift, C, n);
    k_gemm<128, 128, true, false, true, false><<<(n + 63) / 64, 256>>>(
        C, gcn_w[2], gcn_b[2], nullptr, nullptr, B,
        mean, sq, scale, shift, bn_g[2], bn_b[2], tick + 2,
        nullptr, nullptr, nullptr, nullptr, n);
    k_gemm<128, 128, false, true, false, true><<<(n + 63) / 64, 256>>>(
        B, gat_w2, nullptr, scale, shift, A,
        nullptr, nullptr, nullptr, nullptr, nullptr, nullptr, nullptr,
        gat_asrc2, gat_adst2, ss, sd, n);
    k_gat_fused<32, 4, true><<<(n + 7) / 8, 256>>>(
        rowptr, pack, ss, sd, A, gat_b2, B, scale, shift, B, n);

    // ----- layer 3: gemm, gather(+bias), fused BN-stats + mean-pool -----
    k_gemm<128, 64, false, false, false, false><<<(n + 127) / 128, 256>>>(
        B, gcn_w[3], nullptr, nullptr, nullptr, A,
        nullptr, nullptr, nullptr, nullptr, nullptr, nullptr, nullptr,
        nullptr, nullptr, nullptr, nullptr, n);
    k_gather<16, true, false, false><<<(n + 15) / 16, 256>>>(
        rowptr, pack, dis, A, gcn_b[3], nullptr, nullptr, C, n);
    k_bn_pool<<<(n + 63) / 64, 256>>>(
        C, batch, mean, sq, bn_g[3], bn_b[3], psum, cnt, tick + 3, out, G, n);
}